// round 6
// baseline (speedup 1.0000x reference)
#include <cuda_runtime.h>
#include <cuda_bf16.h>
#include <math.h>
#include <stdint.h>

// Problem constants
#define T_TOK 8192
#define D_IN  2048
#define N_QKV 4096
#define Hh    16
#define KVHh  8
#define DHh   128
#define Bb    4
#define Ll    2048
#define Cc    64

// Scratch (device globals: allocation-free per harness rules)
__device__ float g_q[(size_t)T_TOK * 2048];
__device__ float g_k[(size_t)T_TOK * 1024];
__device__ float g_g[(size_t)T_TOK * 1024];
__device__ float g_v[(size_t)T_TOK * 1024];
// bf16 split operands
__device__ __align__(1024) __nv_bfloat16 g_xbf[2ull * T_TOK * D_IN];   // [hv][8192][2048]
__device__ __align__(1024) __nv_bfloat16 g_wtbf[2ull * N_QKV * D_IN];  // [hv][4096][2048] (W^T)

// ================= helpers =================
__device__ __forceinline__ uint32_t smem_to_u32(const void* p) {
    uint32_t a;
    asm("{ .reg .u64 t; cvta.to.shared.u64 t, %1; cvt.u32.u64 %0, t; }" : "=r"(a) : "l"(p));
    return a;
}
__device__ __forceinline__ void cp16(uint32_t dst, const void* src) {
    asm volatile("cp.async.cg.shared.global [%0], [%1], 16;\n" :: "r"(dst), "l"(src));
}
__device__ __forceinline__ void cp_commit() { asm volatile("cp.async.commit_group;\n" ::: "memory"); }
__device__ __forceinline__ void ldsm4(uint32_t* r, uint32_t addr) {
    asm volatile("ldmatrix.sync.aligned.m8n8.x4.shared.b16 {%0,%1,%2,%3}, [%4];"
        : "=r"(r[0]), "=r"(r[1]), "=r"(r[2]), "=r"(r[3]) : "r"(addr));
}
__device__ __forceinline__ void ldsm4t(uint32_t* r, uint32_t addr) {
    asm volatile("ldmatrix.sync.aligned.m8n8.x4.trans.shared.b16 {%0,%1,%2,%3}, [%4];"
        : "=r"(r[0]), "=r"(r[1]), "=r"(r[2]), "=r"(r[3]) : "r"(addr));
}
__device__ __forceinline__ void mma_bf16(float* d, const uint32_t* a, const uint32_t* b) {
    asm volatile("mma.sync.aligned.m16n8k16.row.col.f32.bf16.bf16.f32 "
        "{%0,%1,%2,%3}, {%4,%5,%6,%7}, {%8,%9}, {%0,%1,%2,%3};"
        : "+f"(d[0]), "+f"(d[1]), "+f"(d[2]), "+f"(d[3])
        : "r"(a[0]), "r"(a[1]), "r"(a[2]), "r"(a[3]), "r"(b[0]), "r"(b[1]));
}
__device__ __forceinline__ uint32_t bfpack(float x, float y) {
    __nv_bfloat162 h = __floats2bfloat162_rn(x, y);
    return *(uint32_t*)&h;
}
__device__ __forceinline__ float2 bfunpack(uint32_t u) {
    return __bfloat1622float2(*(__nv_bfloat162*)&u);
}

// ================= Prep kernels =================
__global__ __launch_bounds__(256) void prep_x(const float* __restrict__ X) {
    size_t i = ((size_t)blockIdx.x * 256 + threadIdx.x) * 4;
    float4 x = *(const float4*)(X + i);
    __nv_bfloat162 h0 = __floats2bfloat162_rn(x.x, x.y);
    __nv_bfloat162 h1 = __floats2bfloat162_rn(x.z, x.w);
    float r0 = x.x - __low2float(h0), r1 = x.y - __high2float(h0);
    float r2 = x.z - __low2float(h1), r3 = x.w - __high2float(h1);
    __nv_bfloat162 l0 = __floats2bfloat162_rn(r0, r1);
    __nv_bfloat162 l1 = __floats2bfloat162_rn(r2, r3);
    __nv_bfloat162* hi = (__nv_bfloat162*)(g_xbf + i);
    __nv_bfloat162* lo = (__nv_bfloat162*)(g_xbf + (size_t)T_TOK * D_IN + i);
    hi[0] = h0; hi[1] = h1;
    lo[0] = l0; lo[1] = l1;
}

__global__ __launch_bounds__(256) void prep_w(const float* __restrict__ W) {
    __shared__ float t[32][33];
    const int n0 = blockIdx.x * 32;
    const int k0 = blockIdx.y * 32;
    const int tx = threadIdx.x & 31, ty = threadIdx.x >> 5;
#pragma unroll
    for (int r = 0; r < 32; r += 8)
        t[ty + r][tx] = W[(size_t)(k0 + ty + r) * N_QKV + n0 + tx];
    __syncthreads();
#pragma unroll
    for (int r = 0; r < 32; r += 8) {
        const int nl = ty + r;
        float x = t[tx][nl];
        __nv_bfloat16 h = __float2bfloat16_rn(x);
        __nv_bfloat16 l = __float2bfloat16_rn(x - __bfloat162float(h));
        const size_t o = (size_t)(n0 + nl) * D_IN + k0 + tx;
        g_wtbf[o] = h;
        g_wtbf[(size_t)N_QKV * D_IN + o] = l;
    }
}

// ================= Kernel 1: QKV GEMM (mma.sync bf16 split) =================
// 4-stage cp.async pipeline, single __syncthreads per chunk, loads before compute.
#define NSTAGE  4
#define ATILE_B 16384
#define STAGE_B 32768
#define GEMM_SMEM (NSTAGE * STAGE_B)

__global__ __launch_bounds__(256) void qkv_gemm_mma(const float* __restrict__ bias) {
    extern __shared__ char smem[];
    const uint32_t sb = smem_to_u32(smem);
    const int tid = threadIdx.x;
    const int lane = tid & 31, wid = tid >> 5;
    const int bm = blockIdx.y * 128;
    const int bn = blockIdx.x * 128;
    const int mw = (wid >> 2) * 64;
    const int nw = (wid & 3) * 32;

    // issues cp16s only; caller commits
    auto load_stage = [&](int c) {
        const uint32_t st = sb + (uint32_t)(c & 3) * STAGE_B;
        const int koff = c * 32;
#pragma unroll
        for (int i = 0; i < 8; i++) {
            const int u = tid + i * 256;
            const int isB = u >> 10;
            const int row = (u >> 3) & 127;
            const int unit = u & 7;
            const int plane = unit >> 2, sub = unit & 3;
            const uint32_t dst = st + (uint32_t)isB * ATILE_B + row * 128 +
                                 (uint32_t)((unit ^ (row & 7)) << 4);
            const __nv_bfloat16* src = isB
                ? (g_wtbf + (size_t)plane * N_QKV * D_IN + (size_t)(bn + row) * D_IN + koff + sub * 8)
                : (g_xbf  + (size_t)plane * T_TOK * D_IN + (size_t)(bm + row) * D_IN + koff + sub * 8);
            cp16(dst, src);
        }
    };

    float acc[4][4][4];
#pragma unroll
    for (int i = 0; i < 4; i++)
#pragma unroll
        for (int j = 0; j < 4; j++)
#pragma unroll
            for (int t = 0; t < 4; t++) acc[i][j][t] = 0.f;

    const int a_r  = mw + (lane & 15);
    const int a_rx = a_r & 7;
    const int ua_hi_base = (lane >> 4);
    const int b_r  = nw + (lane & 7) + ((lane >> 4) << 3);
    const int b_rx = b_r & 7;
    const int ub_hi_base = ((lane >> 3) & 1);

    load_stage(0); cp_commit();
    load_stage(1); cp_commit();
    load_stage(2); cp_commit();

    for (int c = 0; c < 64; c++) {
        asm volatile("cp.async.wait_group 2;" ::: "memory");
        __syncthreads();
        // issue next stage's loads immediately (stage (c+3)&3 aliases stage
        // (c-1)&3, whose readers all passed the sync above)
        if (c + 3 < 64) load_stage(c + 3);
        cp_commit();   // empty group in the tail keeps wait_group 2 uniform

        const uint32_t st = sb + (uint32_t)(c & 3) * STAGE_B;
        const uint32_t stB = st + ATILE_B;
#pragma unroll
        for (int ks = 0; ks < 2; ks++) {
            const int ua = ks * 2 + ua_hi_base;
            const int ub = ks * 2 + ub_hi_base;
            uint32_t Ah[4][4], Al[4][4], Bh[2][4], Bl[2][4];
#pragma unroll
            for (int i = 0; i < 4; i++) {
                const uint32_t rowb = st + (uint32_t)(a_r + i * 16) * 128;
                ldsm4(Ah[i], rowb + (uint32_t)((ua ^ a_rx) << 4));
                ldsm4(Al[i], rowb + (uint32_t)(((ua + 4) ^ a_rx) << 4));
            }
#pragma unroll
            for (int p = 0; p < 2; p++) {
                const uint32_t rowb = stB + (uint32_t)(b_r + p * 16) * 128;
                ldsm4(Bh[p], rowb + (uint32_t)((ub ^ b_rx) << 4));
                ldsm4(Bl[p], rowb + (uint32_t)(((ub + 4) ^ b_rx) << 4));
            }
#pragma unroll
            for (int i = 0; i < 4; i++) {
#pragma unroll
                for (int j = 0; j < 4; j++) {
                    const uint32_t* bh = &Bh[j >> 1][(j & 1) * 2];
                    const uint32_t* bl = &Bl[j >> 1][(j & 1) * 2];
                    mma_bf16(acc[i][j], Ah[i], bh);
                    mma_bf16(acc[i][j], Ah[i], bl);
                    mma_bf16(acc[i][j], Al[i], bh);
                }
            }
        }
    }

    const int ml = bm + mw + (lane >> 2);
    const int nl0 = bn + nw + (lane & 3) * 2;
    const int region = (bn < 2048) ? 0 : (bn < 3072 ? 1 : 2);

#pragma unroll
    for (int j = 0; j < 4; j++) {
        const int n = nl0 + j * 8;
        const float b0 = __ldg(bias + n), b1 = __ldg(bias + n + 1);
#pragma unroll
        for (int i = 0; i < 4; i++) {
#pragma unroll
            for (int half = 0; half < 2; half++) {
                const int m = ml + i * 16 + half * 8;
                const float v0 = acc[i][j][half * 2 + 0] + b0;
                const float v1 = acc[i][j][half * 2 + 1] + b1;
                if (region == 0) {
                    float2 o = make_float2(fmaxf(v0, 0.f) * 0.08838834764831845f,
                                           fmaxf(v1, 0.f) * 0.08838834764831845f);
                    *(float2*)&g_q[(size_t)m * 2048 + n] = o;
                } else if (region == 1) {
                    const int cc = n - 2048;
                    float s0 = fminf(__fdividef(1.f, 1.f + __expf(-v0)), 0.95f);
                    float s1 = fminf(__fdividef(1.f, 1.f + __expf(-v1)), 0.95f);
                    *(float2*)&g_k[(size_t)m * 1024 + cc] = make_float2(s0, s1);
                    *(float2*)&g_g[(size_t)m * 1024 + cc] = make_float2(__logf(1.f - s0), __logf(1.f - s1));
                } else {
                    *(float2*)&g_v[(size_t)m * 1024 + (n - 3072)] = make_float2(v0, v1);
                }
            }
        }
    }
}

// ================= Kernel 2: chunked GLA scan (tensor-core) =================
#define BC_OFF   0
#define R_OFF    33792
#define ER_OFF   34304
#define FB_OFF   34816
#define PAN_OFF  35328
#define PANEL(i) (PAN_OFF + (i) * 8192)
#define GLA_SMEM (PAN_OFF + 20 * 8192)
#define POFF(r, c) ((r) * 128 + ((((c) >> 3) ^ ((r) & 7)) << 4) + (((c) & 7) * 2))
#define PADDR(pi, r, u) (sb + PANEL(pi) + (r) * 128 + ((((u) ^ ((r) & 7))) << 4))

__global__ __launch_bounds__(256) void gla_attn(const float* __restrict__ kvc,
                                                const int* __restrict__ sidx,
                                                float* __restrict__ out) {
    extern __shared__ char smem[];
    const uint32_t sb = smem_to_u32(smem);
    float* sBc = (float*)(smem + BC_OFF);
    float* sR  = (float*)(smem + R_OFF);
    float* sER = (float*)(smem + ER_OFF);
    float* sFB = (float*)(smem + FB_OFF);

    const int vh  = blockIdx.x;
    const int h   = blockIdx.y;
    const int b   = blockIdx.z;
    const int kvh = h >> 1;
    const int tid = threadIdx.x;
    const int lane = tid & 31, wid = tid >> 5;
    const int mw = (wid >> 1) * 16;
    const int nw = (wid & 1) * 32;
    const int kw = wid * 16;
    const int skh = kw >> 6;
    const int kwl = kw & 63;
    const int rA = lane & 15, sA_ = lane >> 4;
    const int rB = (lane & 7) | ((lane >> 4) << 3);
    const int sB_ = (lane >> 3) & 1;
    const int fr = lane >> 2, fc = (lane & 3) * 2;

    // ---- init S (bf16 hi/lo) from kv_cache ----
    {
        const int slot = sidx[b];
        const float* Sg = kvc + ((size_t)slot * Hh + h) * DHh * DHh + vh * 64;
#pragma unroll
        for (int t = 0; t < 8; t++) {
            const int u = tid + t * 256;
            const int k = u >> 4, v4 = (u & 15) << 2;
            float4 s4 = *(const float4*)(Sg + (size_t)k * DHh + v4);
            uint32_t h0 = bfpack(s4.x, s4.y), h1 = bfpack(s4.z, s4.w);
            float2 hf0 = bfunpack(h0), hf1 = bfunpack(h1);
            uint32_t l0 = bfpack(s4.x - hf0.x, s4.y - hf0.y);
            uint32_t l1 = bfpack(s4.z - hf1.x, s4.w - hf1.y);
            const int off = POFF(k & 63, v4);
            *(uint2*)(smem + PANEL(12 + (k >> 6)) + off) = make_uint2(h0, h1);
            *(uint2*)(smem + PANEL(12 + 2 + (k >> 6)) + off) = make_uint2(l0, l1);
        }
    }
    __syncthreads();

    const float* qbase = g_q + (size_t)b * Ll * 2048 + h * DHh;
    const float* kbase = g_k + (size_t)b * Ll * 1024 + kvh * DHh;
    const float* gbase = g_g + (size_t)b * Ll * 1024 + kvh * DHh;
    const float* vbase = g_v + (size_t)b * Ll * 1024 + kvh * DHh + vh * 64;
    float* obase = out + (size_t)b * Ll * 2048 + h * DHh + vh * 64;

    for (int ch = 0; ch < 32; ch++) {
        const size_t row0 = (size_t)ch * 64;

        // ---- phase A: load g tile ----
#pragma unroll
        for (int t = 0; t < 8; t++) {
            const int u = tid + t * 256;
            const int i = u >> 5, k4 = (u & 31) << 2;
            float4 gv = *(const float4*)(gbase + (row0 + i) * 1024 + k4);
            *(float4*)&sBc[i * 132 + k4] = gv;
        }
        __syncthreads();

        // ---- phase B: cumsum (two threads per k-column) ----
        if (tid < 128) {
            const int k = tid;
            float run = 0.f;
#pragma unroll
            for (int r = 0; r < 32; r++) {
                run += sBc[r * 132 + k];
                sBc[r * 132 + k] = run;
            }
            sR[k] = run;
            sER[k] = __expf(run);
        } else {
            const int k = tid - 128;
            float run = 0.f;
#pragma unroll
            for (int r = 32; r < 64; r++) {
                run += sBc[r * 132 + k];
                sBc[r * 132 + k] = run;
            }
            sFB[k] = __expf(run);
        }
        __syncthreads();

        // ---- phase C: exponential scalings -> bf16 hi/lo panels ----
#pragma unroll
        for (int t = 0; t < 8; t++) {
            const int u = tid + t * 256;
            const int i = u >> 5, k4 = (u & 31) << 2;
            float4 q4 = *(const float4*)(qbase + (row0 + i) * 2048 + k4);
            float4 kq = *(const float4*)(kbase + (row0 + i) * 1024 + k4);
            float qe[4], qe2[4], kd[4];
#pragma unroll
            for (int j = 0; j < 4; j++) {
                const int k = k4 + j;
                float st = sBc[i * 132 + k];
                float d = (i < 32) ? (st - sR[k]) : st;
                float e1 = __expf(fminf(d, 85.f));
                float e2 = __expf(fminf(-d, 85.f));
                float qv = (j == 0 ? q4.x : j == 1 ? q4.y : j == 2 ? q4.z : q4.w);
                float kv = (j == 0 ? kq.x : j == 1 ? kq.y : j == 2 ? kq.z : kq.w);
                qe2[j] = qv * e1;
                qe[j]  = qe2[j] * sER[k];
                kd[j]  = kv * e2;
            }
            const int kh = k4 >> 6, c = k4 & 63;
            const int off = POFF(i, c);
            {
                uint32_t h0 = bfpack(qe[0], qe[1]), h1 = bfpack(qe[2], qe[3]);
                float2 f0 = bfunpack(h0), f1 = bfunpack(h1);
                uint32_t l0 = bfpack(qe[0] - f0.x, qe[1] - f0.y);
                uint32_t l1 = bfpack(qe[2] - f1.x, qe[3] - f1.y);
                *(uint2*)(smem + PANEL(0 + kh) + off) = make_uint2(h0, h1);
                *(uint2*)(smem + PANEL(2 + kh) + off) = make_uint2(l0, l1);
            }
            {
                uint32_t h0 = bfpack(qe2[0], qe2[1]), h1 = bfpack(qe2[2], qe2[3]);
                float2 f0 = bfunpack(h0), f1 = bfunpack(h1);
                uint32_t l0 = bfpack(qe2[0] - f0.x, qe2[1] - f0.y);
                uint32_t l1 = bfpack(qe2[2] - f1.x, qe2[3] - f1.y);
                *(uint2*)(smem + PANEL(4 + kh) + off) = make_uint2(h0, h1);
                *(uint2*)(smem + PANEL(6 + kh) + off) = make_uint2(l0, l1);
            }
            {
                uint32_t h0 = bfpack(kd[0], kd[1]), h1 = bfpack(kd[2], kd[3]);
                float2 f0 = bfunpack(h0), f1 = bfunpack(h1);
                uint32_t l0 = bfpack(kd[0] - f0.x, kd[1] - f0.y);
                uint32_t l1 = bfpack(kd[2] - f1.x, kd[3] - f1.y);
                *(uint2*)(smem + PANEL(8 + kh) + off) = make_uint2(h0, h1);
                *(uint2*)(smem + PANEL(10 + kh) + off) = make_uint2(l0, l1);
            }
        }
#pragma unroll
        for (int t = 0; t < 4; t++) {
            const int u = tid + t * 256;
            const int i = u >> 4, v4 = (u & 15) << 2;
            float4 vv = *(const float4*)(vbase + (row0 + i) * 1024 + v4);
            uint32_t h0 = bfpack(vv.x, vv.y), h1 = bfpack(vv.z, vv.w);
            float2 f0 = bfunpack(h0), f1 = bfunpack(h1);
            uint32_t l0 = bfpack(vv.x - f0.x, vv.y - f0.y);
            uint32_t l1 = bfpack(vv.z - f1.x, vv.w - f1.y);
            const int off = POFF(i, v4);
            *(uint2*)(smem + PANEL(16) + off) = make_uint2(h0, h1);
            *(uint2*)(smem + PANEL(17) + off) = make_uint2(l0, l1);
        }
        __syncthreads();

        // ---- phase D: GEMM2 (A = Qe2 @ Kd^T) + GEMM1 (o = Qe @ S) ----
        float accO[4][4];
        {
            float acc2[4][4];
#pragma unroll
            for (int t = 0; t < 4; t++)
#pragma unroll
                for (int e = 0; e < 4; e++) acc2[t][e] = 0.f;
#pragma unroll
            for (int kk = 0; kk < 8; kk++) {
                const int kh = kk >> 2, u0 = (kk & 3) * 2;
                uint32_t Ah[4], Al[4];
                ldsm4(Ah, PADDR(4 + kh, mw + rA, u0 + sA_));
                ldsm4(Al, PADDR(6 + kh, mw + rA, u0 + sA_));
#pragma unroll
                for (int g = 0; g < 2; g++) {
                    uint32_t Bh[4], Bl[4];
                    const int rowb = nw + g * 16 + rB;
                    ldsm4(Bh, PADDR(8 + kh, rowb, u0 + sB_));
                    ldsm4(Bl, PADDR(10 + kh, rowb, u0 + sB_));
#pragma unroll
                    for (int n8 = 0; n8 < 2; n8++) {
                        float* d = acc2[g * 2 + n8];
                        mma_bf16(d, Ah, Bh + n8 * 2);
                        mma_bf16(d, Ah, Bl + n8 * 2);
                        mma_bf16(d, Al, Bh + n8 * 2);
                    }
                }
            }
#pragma unroll
            for (int t = 0; t < 4; t++) {
                const int j = nw + t * 8 + fc;
#pragma unroll
                for (int half = 0; half < 2; half++) {
                    const int i = mw + fr + half * 8;
                    float x = (j <= i) ? acc2[t][half * 2 + 0] : 0.f;
                    float y = (j + 1 <= i) ? acc2[t][half * 2 + 1] : 0.f;
                    uint32_t hb = bfpack(x, y);
                    float2 hf = bfunpack(hb);
                    uint32_t lb = bfpack(x - hf.x, y - hf.y);
                    const int off = POFF(i, j);
                    *(uint32_t*)(smem + PANEL(18) + off) = hb;
                    *(uint32_t*)(smem + PANEL(19) + off) = lb;
                }
            }
#pragma unroll
            for (int t = 0; t < 4; t++)
#pragma unroll
                for (int e = 0; e < 4; e++) accO[t][e] = 0.f;
#pragma unroll
            for (int kk = 0; kk < 8; kk++) {
                const int kh = kk >> 2, u0 = (kk & 3) * 2;
                uint32_t Ah[4], Al[4];
                ldsm4(Ah, PADDR(0 + kh, mw + rA, u0 + sA_));
                ldsm4(Al, PADDR(2 + kh, mw + rA, u0 + sA_));
                const int rowS = (kk & 3) * 16 + rA;
#pragma unroll
                for (int g = 0; g < 2; g++) {
                    const int un = (nw >> 3) + g * 2 + sA_;
                    uint32_t Bh[4], Bl[4];
                    ldsm4t(Bh, PADDR(12 + kh, rowS, un));
                    ldsm4t(Bl, PADDR(14 + kh, rowS, un));
#pragma unroll
                    for (int n8 = 0; n8 < 2; n8++) {
                        float* d = accO[g * 2 + n8];
                        mma_bf16(d, Ah, Bh + n8 * 2);
                        mma_bf16(d, Ah, Bl + n8 * 2);
                        mma_bf16(d, Al, Bh + n8 * 2);
                    }
                }
            }
        }
        __syncthreads();

        // ---- phase F: GEMM3 (o += A @ V); write o; state update ----
        // (phase E removed: fb is folded into the state accumulator instead)
#pragma unroll
        for (int kk = 0; kk < 4; kk++) {
            const int u0 = kk * 2;
            uint32_t Ah[4], Al[4];
            ldsm4(Ah, PADDR(18, mw + rA, u0 + sA_));
            ldsm4(Al, PADDR(19, mw + rA, u0 + sA_));
            const int rowV = kk * 16 + rA;
#pragma unroll
            for (int g = 0; g < 2; g++) {
                const int un = (nw >> 3) + g * 2 + sA_;
                uint32_t Bh[4], Bl[4];
                ldsm4t(Bh, PADDR(16, rowV, un));
                ldsm4t(Bl, PADDR(17, rowV, un));
#pragma unroll
                for (int n8 = 0; n8 < 2; n8++) {
                    float* d = accO[g * 2 + n8];
                    mma_bf16(d, Ah, Bh + n8 * 2);
                    mma_bf16(d, Ah, Bl + n8 * 2);
                    mma_bf16(d, Al, Bh + n8 * 2);
                }
            }
        }
#pragma unroll
        for (int t = 0; t < 4; t++) {
            const int v = nw + t * 8 + fc;
#pragma unroll
            for (int half = 0; half < 2; half++) {
                const int i = mw + fr + half * 8;
                *(float2*)(obase + (row0 + i) * 2048 + v) =
                    make_float2(accO[t][half * 2], accO[t][half * 2 + 1]);
            }
        }
        // state update: accS = eR*S; accS += Kd^T @ V; accS *= fb
        // => S_new = eR*fb*S + fb*(Kd^T V) = e^(b_last)*S + Kg^T V
        {
            float accS[8][4];
#pragma unroll
            for (int half = 0; half < 2; half++) {
                const int krow = kw + fr + half * 8;
                const float er = sER[krow];
#pragma unroll
                for (int t = 0; t < 8; t++) {
                    const int v = t * 8 + fc;
                    const int off = POFF(krow & 63, v);
                    float2 hf = bfunpack(*(uint32_t*)(smem + PANEL(12 + skh) + off));
                    float2 lf = bfunpack(*(uint32_t*)(smem + PANEL(14 + skh) + off));
                    accS[t][half * 2 + 0] = (hf.x + lf.x) * er;
                    accS[t][half * 2 + 1] = (hf.y + lf.y) * er;
                }
            }
#pragma unroll
            for (int kk = 0; kk < 4; kk++) {
                const int rowJ = rB + kk * 16;
                const int unM = (kwl >> 3) + sB_;
                uint32_t Ah[4], Al[4];
                ldsm4t(Ah, PADDR(8 + skh, rowJ, unM));
                ldsm4t(Al, PADDR(10 + skh, rowJ, unM));
                const int rowV = kk * 16 + rA;
#pragma unroll
                for (int g = 0; g < 4; g++) {
                    const int un = g * 2 + sA_;
                    uint32_t Bh[4], Bl[4];
                    ldsm4t(Bh, PADDR(16, rowV, un));
                    ldsm4t(Bl, PADDR(17, rowV, un));
#pragma unroll
                    for (int n8 = 0; n8 < 2; n8++) {
                        float* d = accS[g * 2 + n8];
                        mma_bf16(d, Ah, Bh + n8 * 2);
                        mma_bf16(d, Ah, Bl + n8 * 2);
                        mma_bf16(d, Al, Bh + n8 * 2);
                    }
                }
            }
#pragma unroll
            for (int half = 0; half < 2; half++) {
                const int krow = kw + fr + half * 8;
                const float fb = sFB[krow];
#pragma unroll
                for (int t = 0; t < 8; t++) {
                    const int v = t * 8 + fc;
                    float x = accS[t][half * 2 + 0] * fb, y = accS[t][half * 2 + 1] * fb;
                    uint32_t hb = bfpack(x, y);
                    float2 hf = bfunpack(hb);
                    uint32_t lb = bfpack(x - hf.x, y - hf.y);
                    const int off = POFF(krow & 63, v);
                    *(uint32_t*)(smem + PANEL(12 + skh) + off) = hb;
                    *(uint32_t*)(smem + PANEL(14 + skh) + off) = lb;
                }
            }
        }
        __syncthreads();
    }
}

// ---------------- launch ----------------
extern "C" void kernel_launch(void* const* d_in, const int* in_sizes, int n_in,
                              void* d_out, int out_size) {
    const float* X    = (const float*)d_in[0];
    const float* W    = (const float*)d_in[1];
    const float* bias = (const float*)d_in[2];
    const float* kvc  = (const float*)d_in[3];
    const int*   sidx = (const int*)d_in[4];
    float* out = (float*)d_out;

    prep_x<<<(T_TOK * D_IN) / (256 * 4), 256>>>(X);
    prep_w<<<dim3(N_QKV / 32, D_IN / 32), 256>>>(W);

    cudaFuncSetAttribute(qkv_gemm_mma, cudaFuncAttributeMaxDynamicSharedMemorySize, GEMM_SMEM);
    dim3 gg(N_QKV / 128, T_TOK / 128);
    qkv_gemm_mma<<<gg, 256, GEMM_SMEM>>>(bias);

    cudaFuncSetAttribute(gla_attn, cudaFuncAttributeMaxDynamicSharedMemorySize, GLA_SMEM);
    dim3 ga(2, Hh, Bb);
    gla_attn<<<ga, 256, GLA_SMEM>>>(kvc, sidx, out);
}

// round 7
// speedup vs baseline: 1.1714x; 1.1714x over previous
#include <cuda_runtime.h>
#include <cuda_bf16.h>
#include <math.h>
#include <stdint.h>

// Problem constants
#define T_TOK 8192
#define D_IN  2048
#define N_QKV 4096
#define Hh    16
#define KVHh  8
#define DHh   128
#define Bb    4
#define Ll    2048
#define Cc    64

// Scratch (device globals: allocation-free per harness rules)
__device__ float g_q[(size_t)T_TOK * 2048];
__device__ float g_k[(size_t)T_TOK * 1024];
__device__ float g_g[(size_t)T_TOK * 1024];
__device__ float g_v[(size_t)T_TOK * 1024];
// bf16 split operands
__device__ __align__(1024) __nv_bfloat16 g_xbf[2ull * T_TOK * D_IN];   // [hv][8192][2048]
__device__ __align__(1024) __nv_bfloat16 g_wtbf[2ull * N_QKV * D_IN];  // [hv][4096][2048] (W^T)

// ================= helpers =================
__device__ __forceinline__ uint32_t smem_to_u32(const void* p) {
    uint32_t a;
    asm("{ .reg .u64 t; cvta.to.shared.u64 t, %1; cvt.u32.u64 %0, t; }" : "=r"(a) : "l"(p));
    return a;
}
__device__ __forceinline__ void cp16(uint32_t dst, const void* src) {
    asm volatile("cp.async.cg.shared.global [%0], [%1], 16;\n" :: "r"(dst), "l"(src));
}
__device__ __forceinline__ void cp_commit() { asm volatile("cp.async.commit_group;\n" ::: "memory"); }
__device__ __forceinline__ void ldsm4(uint32_t* r, uint32_t addr) {
    asm volatile("ldmatrix.sync.aligned.m8n8.x4.shared.b16 {%0,%1,%2,%3}, [%4];"
        : "=r"(r[0]), "=r"(r[1]), "=r"(r[2]), "=r"(r[3]) : "r"(addr));
}
__device__ __forceinline__ void ldsm4t(uint32_t* r, uint32_t addr) {
    asm volatile("ldmatrix.sync.aligned.m8n8.x4.trans.shared.b16 {%0,%1,%2,%3}, [%4];"
        : "=r"(r[0]), "=r"(r[1]), "=r"(r[2]), "=r"(r[3]) : "r"(addr));
}
__device__ __forceinline__ void mma_bf16(float* d, const uint32_t* a, const uint32_t* b) {
    asm volatile("mma.sync.aligned.m16n8k16.row.col.f32.bf16.bf16.f32 "
        "{%0,%1,%2,%3}, {%4,%5,%6,%7}, {%8,%9}, {%0,%1,%2,%3};"
        : "+f"(d[0]), "+f"(d[1]), "+f"(d[2]), "+f"(d[3])
        : "r"(a[0]), "r"(a[1]), "r"(a[2]), "r"(a[3]), "r"(b[0]), "r"(b[1]));
}
__device__ __forceinline__ uint32_t bfpack(float x, float y) {
    __nv_bfloat162 h = __floats2bfloat162_rn(x, y);
    return *(uint32_t*)&h;
}
__device__ __forceinline__ float2 bfunpack(uint32_t u) {
    return __bfloat1622float2(*(__nv_bfloat162*)&u);
}

// ================= Prep kernels =================
__global__ __launch_bounds__(256) void prep_x(const float* __restrict__ X) {
    size_t i = ((size_t)blockIdx.x * 256 + threadIdx.x) * 4;
    float4 x = *(const float4*)(X + i);
    __nv_bfloat162 h0 = __floats2bfloat162_rn(x.x, x.y);
    __nv_bfloat162 h1 = __floats2bfloat162_rn(x.z, x.w);
    float r0 = x.x - __low2float(h0), r1 = x.y - __high2float(h0);
    float r2 = x.z - __low2float(h1), r3 = x.w - __high2float(h1);
    __nv_bfloat162 l0 = __floats2bfloat162_rn(r0, r1);
    __nv_bfloat162 l1 = __floats2bfloat162_rn(r2, r3);
    __nv_bfloat162* hi = (__nv_bfloat162*)(g_xbf + i);
    __nv_bfloat162* lo = (__nv_bfloat162*)(g_xbf + (size_t)T_TOK * D_IN + i);
    hi[0] = h0; hi[1] = h1;
    lo[0] = l0; lo[1] = l1;
}

__global__ __launch_bounds__(256) void prep_w(const float* __restrict__ W) {
    __shared__ float t[32][33];
    const int n0 = blockIdx.x * 32;
    const int k0 = blockIdx.y * 32;
    const int tx = threadIdx.x & 31, ty = threadIdx.x >> 5;
#pragma unroll
    for (int r = 0; r < 32; r += 8)
        t[ty + r][tx] = W[(size_t)(k0 + ty + r) * N_QKV + n0 + tx];
    __syncthreads();
#pragma unroll
    for (int r = 0; r < 32; r += 8) {
        const int nl = ty + r;
        float x = t[tx][nl];
        __nv_bfloat16 h = __float2bfloat16_rn(x);
        __nv_bfloat16 l = __float2bfloat16_rn(x - __bfloat162float(h));
        const size_t o = (size_t)(n0 + nl) * D_IN + k0 + tx;
        g_wtbf[o] = h;
        g_wtbf[(size_t)N_QKV * D_IN + o] = l;
    }
}

// ================= Kernel 1: QKV GEMM (mma.sync bf16 split) =================
// 2-stage cp.async pipeline, 2 CTAs/SM, one sync + one commit group per chunk.
#define NSTAGE  2
#define ATILE_B 16384
#define STAGE_B 32768
#define GEMM_SMEM (NSTAGE * STAGE_B)

__global__ __launch_bounds__(256, 2) void qkv_gemm_mma(const float* __restrict__ bias) {
    extern __shared__ char smem[];
    const uint32_t sb = smem_to_u32(smem);
    const int tid = threadIdx.x;
    const int lane = tid & 31, wid = tid >> 5;
    const int bm = blockIdx.y * 128;
    const int bn = blockIdx.x * 128;
    const int mw = (wid >> 2) * 64;
    const int nw = (wid & 3) * 32;

    // issues cp16s only; caller commits
    auto load_stage = [&](int c) {
        const uint32_t st = sb + (uint32_t)(c & 1) * STAGE_B;
        const int koff = c * 32;
#pragma unroll
        for (int i = 0; i < 8; i++) {
            const int u = tid + i * 256;
            const int isB = u >> 10;
            const int row = (u >> 3) & 127;
            const int unit = u & 7;
            const int plane = unit >> 2, sub = unit & 3;
            const uint32_t dst = st + (uint32_t)isB * ATILE_B + row * 128 +
                                 (uint32_t)((unit ^ (row & 7)) << 4);
            const __nv_bfloat16* src = isB
                ? (g_wtbf + (size_t)plane * N_QKV * D_IN + (size_t)(bn + row) * D_IN + koff + sub * 8)
                : (g_xbf  + (size_t)plane * T_TOK * D_IN + (size_t)(bm + row) * D_IN + koff + sub * 8);
            cp16(dst, src);
        }
    };

    float acc[4][4][4];
#pragma unroll
    for (int i = 0; i < 4; i++)
#pragma unroll
        for (int j = 0; j < 4; j++)
#pragma unroll
            for (int t = 0; t < 4; t++) acc[i][j][t] = 0.f;

    const int a_r  = mw + (lane & 15);
    const int a_rx = a_r & 7;
    const int ua_hi_base = (lane >> 4);
    const int b_r  = nw + (lane & 7) + ((lane >> 4) << 3);
    const int b_rx = b_r & 7;
    const int ub_hi_base = ((lane >> 3) & 1);

    load_stage(0); cp_commit();

    for (int c = 0; c < 64; c++) {
        asm volatile("cp.async.wait_group 0;" ::: "memory");
        __syncthreads();
        // stage (c+1)&1's previous readers all finished compute(c-1) before
        // passing the sync above, so overwriting it now is safe.
        if (c + 1 < 64) { load_stage(c + 1); cp_commit(); }

        const uint32_t st = sb + (uint32_t)(c & 1) * STAGE_B;
        const uint32_t stB = st + ATILE_B;
#pragma unroll
        for (int ks = 0; ks < 2; ks++) {
            const int ua = ks * 2 + ua_hi_base;
            const int ub = ks * 2 + ub_hi_base;
            uint32_t Bh[2][4], Bl[2][4];
#pragma unroll
            for (int p = 0; p < 2; p++) {
                const uint32_t rowb = stB + (uint32_t)(b_r + p * 16) * 128;
                ldsm4(Bh[p], rowb + (uint32_t)((ub ^ b_rx) << 4));
                ldsm4(Bl[p], rowb + (uint32_t)(((ub + 4) ^ b_rx) << 4));
            }
#pragma unroll
            for (int i = 0; i < 4; i++) {
                uint32_t Ah[4], Al[4];
                const uint32_t rowb = st + (uint32_t)(a_r + i * 16) * 128;
                ldsm4(Ah, rowb + (uint32_t)((ua ^ a_rx) << 4));
                ldsm4(Al, rowb + (uint32_t)(((ua + 4) ^ a_rx) << 4));
#pragma unroll
                for (int j = 0; j < 4; j++) {
                    const uint32_t* bh = &Bh[j >> 1][(j & 1) * 2];
                    const uint32_t* bl = &Bl[j >> 1][(j & 1) * 2];
                    mma_bf16(acc[i][j], Ah, bh);
                    mma_bf16(acc[i][j], Ah, bl);
                    mma_bf16(acc[i][j], Al, bh);
                }
            }
        }
        // no trailing sync: the next iteration's top sync (after wait_group)
        // orders all readers of this stage before its next overwrite.
        __syncthreads();
    }

    const int ml = bm + mw + (lane >> 2);
    const int nl0 = bn + nw + (lane & 3) * 2;
    const int region = (bn < 2048) ? 0 : (bn < 3072 ? 1 : 2);

#pragma unroll
    for (int j = 0; j < 4; j++) {
        const int n = nl0 + j * 8;
        const float b0 = __ldg(bias + n), b1 = __ldg(bias + n + 1);
#pragma unroll
        for (int i = 0; i < 4; i++) {
#pragma unroll
            for (int half = 0; half < 2; half++) {
                const int m = ml + i * 16 + half * 8;
                const float v0 = acc[i][j][half * 2 + 0] + b0;
                const float v1 = acc[i][j][half * 2 + 1] + b1;
                if (region == 0) {
                    float2 o = make_float2(fmaxf(v0, 0.f) * 0.08838834764831845f,
                                           fmaxf(v1, 0.f) * 0.08838834764831845f);
                    *(float2*)&g_q[(size_t)m * 2048 + n] = o;
                } else if (region == 1) {
                    const int cc = n - 2048;
                    float s0 = fminf(__fdividef(1.f, 1.f + __expf(-v0)), 0.95f);
                    float s1 = fminf(__fdividef(1.f, 1.f + __expf(-v1)), 0.95f);
                    *(float2*)&g_k[(size_t)m * 1024 + cc] = make_float2(s0, s1);
                    *(float2*)&g_g[(size_t)m * 1024 + cc] = make_float2(__logf(1.f - s0), __logf(1.f - s1));
                } else {
                    *(float2*)&g_v[(size_t)m * 1024 + (n - 3072)] = make_float2(v0, v1);
                }
            }
        }
    }
}

// ================= Kernel 2: chunked GLA scan (tensor-core) =================
#define BC_OFF   0
#define R_OFF    33792
#define ER_OFF   34304
#define FB_OFF   34816
#define PAN_OFF  35328
#define PANEL(i) (PAN_OFF + (i) * 8192)
#define GLA_SMEM (PAN_OFF + 20 * 8192)
#define POFF(r, c) ((r) * 128 + ((((c) >> 3) ^ ((r) & 7)) << 4) + (((c) & 7) * 2))
#define PADDR(pi, r, u) (sb + PANEL(pi) + (r) * 128 + ((((u) ^ ((r) & 7))) << 4))

__global__ __launch_bounds__(256) void gla_attn(const float* __restrict__ kvc,
                                                const int* __restrict__ sidx,
                                                float* __restrict__ out) {
    extern __shared__ char smem[];
    const uint32_t sb = smem_to_u32(smem);
    float* sBc = (float*)(smem + BC_OFF);
    float* sR  = (float*)(smem + R_OFF);
    float* sER = (float*)(smem + ER_OFF);
    float* sFB = (float*)(smem + FB_OFF);

    const int vh  = blockIdx.x;
    const int h   = blockIdx.y;
    const int b   = blockIdx.z;
    const int kvh = h >> 1;
    const int tid = threadIdx.x;
    const int lane = tid & 31, wid = tid >> 5;
    const int mw = (wid >> 1) * 16;
    const int nw = (wid & 1) * 32;
    const int kw = wid * 16;
    const int skh = kw >> 6;
    const int kwl = kw & 63;
    const int rA = lane & 15, sA_ = lane >> 4;
    const int rB = (lane & 7) | ((lane >> 4) << 3);
    const int sB_ = (lane >> 3) & 1;
    const int fr = lane >> 2, fc = (lane & 3) * 2;

    // ---- init S (bf16 hi/lo) from kv_cache ----
    {
        const int slot = sidx[b];
        const float* Sg = kvc + ((size_t)slot * Hh + h) * DHh * DHh + vh * 64;
#pragma unroll
        for (int t = 0; t < 8; t++) {
            const int u = tid + t * 256;
            const int k = u >> 4, v4 = (u & 15) << 2;
            float4 s4 = *(const float4*)(Sg + (size_t)k * DHh + v4);
            uint32_t h0 = bfpack(s4.x, s4.y), h1 = bfpack(s4.z, s4.w);
            float2 hf0 = bfunpack(h0), hf1 = bfunpack(h1);
            uint32_t l0 = bfpack(s4.x - hf0.x, s4.y - hf0.y);
            uint32_t l1 = bfpack(s4.z - hf1.x, s4.w - hf1.y);
            const int off = POFF(k & 63, v4);
            *(uint2*)(smem + PANEL(12 + (k >> 6)) + off) = make_uint2(h0, h1);
            *(uint2*)(smem + PANEL(12 + 2 + (k >> 6)) + off) = make_uint2(l0, l1);
        }
    }
    __syncthreads();

    const float* qbase = g_q + (size_t)b * Ll * 2048 + h * DHh;
    const float* kbase = g_k + (size_t)b * Ll * 1024 + kvh * DHh;
    const float* gbase = g_g + (size_t)b * Ll * 1024 + kvh * DHh;
    const float* vbase = g_v + (size_t)b * Ll * 1024 + kvh * DHh + vh * 64;
    float* obase = out + (size_t)b * Ll * 2048 + h * DHh + vh * 64;

    for (int ch = 0; ch < 32; ch++) {
        const size_t row0 = (size_t)ch * 64;

        // ---- phase A: load g tile ----
#pragma unroll
        for (int t = 0; t < 8; t++) {
            const int u = tid + t * 256;
            const int i = u >> 5, k4 = (u & 31) << 2;
            float4 gv = *(const float4*)(gbase + (row0 + i) * 1024 + k4);
            *(float4*)&sBc[i * 132 + k4] = gv;
        }
        __syncthreads();

        // ---- phase B: cumsum (two threads per k-column) ----
        if (tid < 128) {
            const int k = tid;
            float run = 0.f;
#pragma unroll
            for (int r = 0; r < 32; r++) {
                run += sBc[r * 132 + k];
                sBc[r * 132 + k] = run;
            }
            sR[k] = run;
            sER[k] = __expf(run);
        } else {
            const int k = tid - 128;
            float run = 0.f;
#pragma unroll
            for (int r = 32; r < 64; r++) {
                run += sBc[r * 132 + k];
                sBc[r * 132 + k] = run;
            }
            sFB[k] = __expf(run);
        }
        __syncthreads();

        // ---- phase C: exponential scalings -> bf16 hi/lo panels ----
#pragma unroll
        for (int t = 0; t < 8; t++) {
            const int u = tid + t * 256;
            const int i = u >> 5, k4 = (u & 31) << 2;
            float4 q4 = *(const float4*)(qbase + (row0 + i) * 2048 + k4);
            float4 kq = *(const float4*)(kbase + (row0 + i) * 1024 + k4);
            float qe[4], qe2[4], kd[4];
#pragma unroll
            for (int j = 0; j < 4; j++) {
                const int k = k4 + j;
                float st = sBc[i * 132 + k];
                float d = (i < 32) ? (st - sR[k]) : st;
                float e1 = __expf(fminf(d, 85.f));
                float e2 = __expf(fminf(-d, 85.f));
                float qv = (j == 0 ? q4.x : j == 1 ? q4.y : j == 2 ? q4.z : q4.w);
                float kv = (j == 0 ? kq.x : j == 1 ? kq.y : j == 2 ? kq.z : kq.w);
                qe2[j] = qv * e1;
                qe[j]  = qe2[j] * sER[k];
                kd[j]  = kv * e2;
            }
            const int kh = k4 >> 6, c = k4 & 63;
            const int off = POFF(i, c);
            {
                uint32_t h0 = bfpack(qe[0], qe[1]), h1 = bfpack(qe[2], qe[3]);
                float2 f0 = bfunpack(h0), f1 = bfunpack(h1);
                uint32_t l0 = bfpack(qe[0] - f0.x, qe[1] - f0.y);
                uint32_t l1 = bfpack(qe[2] - f1.x, qe[3] - f1.y);
                *(uint2*)(smem + PANEL(0 + kh) + off) = make_uint2(h0, h1);
                *(uint2*)(smem + PANEL(2 + kh) + off) = make_uint2(l0, l1);
            }
            {
                uint32_t h0 = bfpack(qe2[0], qe2[1]), h1 = bfpack(qe2[2], qe2[3]);
                float2 f0 = bfunpack(h0), f1 = bfunpack(h1);
                uint32_t l0 = bfpack(qe2[0] - f0.x, qe2[1] - f0.y);
                uint32_t l1 = bfpack(qe2[2] - f1.x, qe2[3] - f1.y);
                *(uint2*)(smem + PANEL(4 + kh) + off) = make_uint2(h0, h1);
                *(uint2*)(smem + PANEL(6 + kh) + off) = make_uint2(l0, l1);
            }
            {
                uint32_t h0 = bfpack(kd[0], kd[1]), h1 = bfpack(kd[2], kd[3]);
                float2 f0 = bfunpack(h0), f1 = bfunpack(h1);
                uint32_t l0 = bfpack(kd[0] - f0.x, kd[1] - f0.y);
                uint32_t l1 = bfpack(kd[2] - f1.x, kd[3] - f1.y);
                *(uint2*)(smem + PANEL(8 + kh) + off) = make_uint2(h0, h1);
                *(uint2*)(smem + PANEL(10 + kh) + off) = make_uint2(l0, l1);
            }
        }
#pragma unroll
        for (int t = 0; t < 4; t++) {
            const int u = tid + t * 256;
            const int i = u >> 4, v4 = (u & 15) << 2;
            float4 vv = *(const float4*)(vbase + (row0 + i) * 1024 + v4);
            uint32_t h0 = bfpack(vv.x, vv.y), h1 = bfpack(vv.z, vv.w);
            float2 f0 = bfunpack(h0), f1 = bfunpack(h1);
            uint32_t l0 = bfpack(vv.x - f0.x, vv.y - f0.y);
            uint32_t l1 = bfpack(vv.z - f1.x, vv.w - f1.y);
            const int off = POFF(i, v4);
            *(uint2*)(smem + PANEL(16) + off) = make_uint2(h0, h1);
            *(uint2*)(smem + PANEL(17) + off) = make_uint2(l0, l1);
        }
        __syncthreads();

        // ---- phase D: GEMM2 (A = Qe2 @ Kd^T) + GEMM1 (o = Qe @ S) ----
        float accO[4][4];
        {
            float acc2[4][4];
#pragma unroll
            for (int t = 0; t < 4; t++)
#pragma unroll
                for (int e = 0; e < 4; e++) acc2[t][e] = 0.f;
#pragma unroll
            for (int kk = 0; kk < 8; kk++) {
                const int kh = kk >> 2, u0 = (kk & 3) * 2;
                uint32_t Ah[4], Al[4];
                ldsm4(Ah, PADDR(4 + kh, mw + rA, u0 + sA_));
                ldsm4(Al, PADDR(6 + kh, mw + rA, u0 + sA_));
#pragma unroll
                for (int g = 0; g < 2; g++) {
                    uint32_t Bh[4], Bl[4];
                    const int rowb = nw + g * 16 + rB;
                    ldsm4(Bh, PADDR(8 + kh, rowb, u0 + sB_));
                    ldsm4(Bl, PADDR(10 + kh, rowb, u0 + sB_));
#pragma unroll
                    for (int n8 = 0; n8 < 2; n8++) {
                        float* d = acc2[g * 2 + n8];
                        mma_bf16(d, Ah, Bh + n8 * 2);
                        mma_bf16(d, Ah, Bl + n8 * 2);
                        mma_bf16(d, Al, Bh + n8 * 2);
                    }
                }
            }
#pragma unroll
            for (int t = 0; t < 4; t++) {
                const int j = nw + t * 8 + fc;
#pragma unroll
                for (int half = 0; half < 2; half++) {
                    const int i = mw + fr + half * 8;
                    float x = (j <= i) ? acc2[t][half * 2 + 0] : 0.f;
                    float y = (j + 1 <= i) ? acc2[t][half * 2 + 1] : 0.f;
                    uint32_t hb = bfpack(x, y);
                    float2 hf = bfunpack(hb);
                    uint32_t lb = bfpack(x - hf.x, y - hf.y);
                    const int off = POFF(i, j);
                    *(uint32_t*)(smem + PANEL(18) + off) = hb;
                    *(uint32_t*)(smem + PANEL(19) + off) = lb;
                }
            }
#pragma unroll
            for (int t = 0; t < 4; t++)
#pragma unroll
                for (int e = 0; e < 4; e++) accO[t][e] = 0.f;
#pragma unroll
            for (int kk = 0; kk < 8; kk++) {
                const int kh = kk >> 2, u0 = (kk & 3) * 2;
                uint32_t Ah[4], Al[4];
                ldsm4(Ah, PADDR(0 + kh, mw + rA, u0 + sA_));
                ldsm4(Al, PADDR(2 + kh, mw + rA, u0 + sA_));
                const int rowS = (kk & 3) * 16 + rA;
#pragma unroll
                for (int g = 0; g < 2; g++) {
                    const int un = (nw >> 3) + g * 2 + sA_;
                    uint32_t Bh[4], Bl[4];
                    ldsm4t(Bh, PADDR(12 + kh, rowS, un));
                    ldsm4t(Bl, PADDR(14 + kh, rowS, un));
#pragma unroll
                    for (int n8 = 0; n8 < 2; n8++) {
                        float* d = accO[g * 2 + n8];
                        mma_bf16(d, Ah, Bh + n8 * 2);
                        mma_bf16(d, Ah, Bl + n8 * 2);
                        mma_bf16(d, Al, Bh + n8 * 2);
                    }
                }
            }
        }
        __syncthreads();

        // ---- phase F: GEMM3 (o += A @ V); write o; state update ----
#pragma unroll
        for (int kk = 0; kk < 4; kk++) {
            const int u0 = kk * 2;
            uint32_t Ah[4], Al[4];
            ldsm4(Ah, PADDR(18, mw + rA, u0 + sA_));
            ldsm4(Al, PADDR(19, mw + rA, u0 + sA_));
            const int rowV = kk * 16 + rA;
#pragma unroll
            for (int g = 0; g < 2; g++) {
                const int un = (nw >> 3) + g * 2 + sA_;
                uint32_t Bh[4], Bl[4];
                ldsm4t(Bh, PADDR(16, rowV, un));
                ldsm4t(Bl, PADDR(17, rowV, un));
#pragma unroll
                for (int n8 = 0; n8 < 2; n8++) {
                    float* d = accO[g * 2 + n8];
                    mma_bf16(d, Ah, Bh + n8 * 2);
                    mma_bf16(d, Ah, Bl + n8 * 2);
                    mma_bf16(d, Al, Bh + n8 * 2);
                }
            }
        }
#pragma unroll
        for (int t = 0; t < 4; t++) {
            const int v = nw + t * 8 + fc;
#pragma unroll
            for (int half = 0; half < 2; half++) {
                const int i = mw + fr + half * 8;
                *(float2*)(obase + (row0 + i) * 2048 + v) =
                    make_float2(accO[t][half * 2], accO[t][half * 2 + 1]);
            }
        }
        // state update: accS = eR*S; accS += Kd^T @ V; accS *= fb
        {
            float accS[8][4];
#pragma unroll
            for (int half = 0; half < 2; half++) {
                const int krow = kw + fr + half * 8;
                const float er = sER[krow];
#pragma unroll
                for (int t = 0; t < 8; t++) {
                    const int v = t * 8 + fc;
                    const int off = POFF(krow & 63, v);
                    float2 hf = bfunpack(*(uint32_t*)(smem + PANEL(12 + skh) + off));
                    float2 lf = bfunpack(*(uint32_t*)(smem + PANEL(14 + skh) + off));
                    accS[t][half * 2 + 0] = (hf.x + lf.x) * er;
                    accS[t][half * 2 + 1] = (hf.y + lf.y) * er;
                }
            }
#pragma unroll
            for (int kk = 0; kk < 4; kk++) {
                const int rowJ = rB + kk * 16;
                const int unM = (kwl >> 3) + sB_;
                uint32_t Ah[4], Al[4];
                ldsm4t(Ah, PADDR(8 + skh, rowJ, unM));
                ldsm4t(Al, PADDR(10 + skh, rowJ, unM));
                const int rowV = kk * 16 + rA;
#pragma unroll
                for (int g = 0; g < 4; g++) {
                    const int un = g * 2 + sA_;
                    uint32_t Bh[4], Bl[4];
                    ldsm4t(Bh, PADDR(16, rowV, un));
                    ldsm4t(Bl, PADDR(17, rowV, un));
#pragma unroll
                    for (int n8 = 0; n8 < 2; n8++) {
                        float* d = accS[g * 2 + n8];
                        mma_bf16(d, Ah, Bh + n8 * 2);
                        mma_bf16(d, Ah, Bl + n8 * 2);
                        mma_bf16(d, Al, Bh + n8 * 2);
                    }
                }
            }
#pragma unroll
            for (int half = 0; half < 2; half++) {
                const int krow = kw + fr + half * 8;
                const float fb = sFB[krow];
#pragma unroll
                for (int t = 0; t < 8; t++) {
                    const int v = t * 8 + fc;
                    float x = accS[t][half * 2 + 0] * fb, y = accS[t][half * 2 + 1] * fb;
                    uint32_t hb = bfpack(x, y);
                    float2 hf = bfunpack(hb);
                    uint32_t lb = bfpack(x - hf.x, y - hf.y);
                    const int off = POFF(krow & 63, v);
                    *(uint32_t*)(smem + PANEL(12 + skh) + off) = hb;
                    *(uint32_t*)(smem + PANEL(14 + skh) + off) = lb;
                }
            }
        }
        __syncthreads();
    }
}

// ---------------- launch ----------------
extern "C" void kernel_launch(void* const* d_in, const int* in_sizes, int n_in,
                              void* d_out, int out_size) {
    const float* X    = (const float*)d_in[0];
    const float* W    = (const float*)d_in[1];
    const float* bias = (const float*)d_in[2];
    const float* kvc  = (const float*)d_in[3];
    const int*   sidx = (const int*)d_in[4];
    float* out = (float*)d_out;

    prep_x<<<(T_TOK * D_IN) / (256 * 4), 256>>>(X);
    prep_w<<<dim3(N_QKV / 32, D_IN / 32), 256>>>(W);

    cudaFuncSetAttribute(qkv_gemm_mma, cudaFuncAttributeMaxDynamicSharedMemorySize, GEMM_SMEM);
    dim3 gg(N_QKV / 128, T_TOK / 128);
    qkv_gemm_mma<<<gg, 256, GEMM_SMEM>>>(bias);

    cudaFuncSetAttribute(gla_attn, cudaFuncAttributeMaxDynamicSharedMemorySize, GLA_SMEM);
    dim3 ga(2, Hh, Bb);
    gla_attn<<<ga, 256, GLA_SMEM>>>(kvc, sidx, out);
}

// round 10
// speedup vs baseline: 1.6135x; 1.3773x over previous
#include <cuda_runtime.h>
#include <cuda_bf16.h>
#include <cuda_fp16.h>
#include <math.h>
#include <stdint.h>

// Problem constants
#define T_TOK 8192
#define D_IN  2048
#define N_QKV 4096
#define Hh    16
#define KVHh  8
#define DHh   128
#define Bb    4
#define Ll    2048
#define Cc    64

// Scratch (device globals: allocation-free per harness rules)
__device__ float g_q[(size_t)T_TOK * 2048];
__device__ float g_k[(size_t)T_TOK * 1024];
__device__ float g_g[(size_t)T_TOK * 1024];
__device__ float g_v[(size_t)T_TOK * 1024];
// fp16 split operands for the QKV GEMM
__device__ __align__(1024) __half g_xhf[2ull * T_TOK * D_IN];    // [hi/lo][8192][2048]
__device__ __align__(1024) __half g_wthf[(size_t)N_QKV * D_IN];  // [4096][2048] (W^T, hi only)

// ================= helpers =================
__device__ __forceinline__ uint32_t smem_to_u32(const void* p) {
    uint32_t a;
    asm("{ .reg .u64 t; cvta.to.shared.u64 t, %1; cvt.u32.u64 %0, t; }" : "=r"(a) : "l"(p));
    return a;
}
__device__ __forceinline__ void cp16(uint32_t dst, const void* src) {
    asm volatile("cp.async.cg.shared.global [%0], [%1], 16;\n" :: "r"(dst), "l"(src));
}
__device__ __forceinline__ void cp_commit() { asm volatile("cp.async.commit_group;\n" ::: "memory"); }
__device__ __forceinline__ void ldsm4(uint32_t* r, uint32_t addr) {
    asm volatile("ldmatrix.sync.aligned.m8n8.x4.shared.b16 {%0,%1,%2,%3}, [%4];"
        : "=r"(r[0]), "=r"(r[1]), "=r"(r[2]), "=r"(r[3]) : "r"(addr));
}
__device__ __forceinline__ void ldsm4t(uint32_t* r, uint32_t addr) {
    asm volatile("ldmatrix.sync.aligned.m8n8.x4.trans.shared.b16 {%0,%1,%2,%3}, [%4];"
        : "=r"(r[0]), "=r"(r[1]), "=r"(r[2]), "=r"(r[3]) : "r"(addr));
}
__device__ __forceinline__ void mma_bf16(float* d, const uint32_t* a, const uint32_t* b) {
    asm volatile("mma.sync.aligned.m16n8k16.row.col.f32.bf16.bf16.f32 "
        "{%0,%1,%2,%3}, {%4,%5,%6,%7}, {%8,%9}, {%0,%1,%2,%3};"
        : "+f"(d[0]), "+f"(d[1]), "+f"(d[2]), "+f"(d[3])
        : "r"(a[0]), "r"(a[1]), "r"(a[2]), "r"(a[3]), "r"(b[0]), "r"(b[1]));
}
__device__ __forceinline__ void mma_fp16(float* d, const uint32_t* a, const uint32_t* b) {
    asm volatile("mma.sync.aligned.m16n8k16.row.col.f32.f16.f16.f32 "
        "{%0,%1,%2,%3}, {%4,%5,%6,%7}, {%8,%9}, {%0,%1,%2,%3};"
        : "+f"(d[0]), "+f"(d[1]), "+f"(d[2]), "+f"(d[3])
        : "r"(a[0]), "r"(a[1]), "r"(a[2]), "r"(a[3]), "r"(b[0]), "r"(b[1]));
}
__device__ __forceinline__ uint32_t bfpack(float x, float y) {
    __nv_bfloat162 h = __floats2bfloat162_rn(x, y);
    return *(uint32_t*)&h;
}
__device__ __forceinline__ float2 bfunpack(uint32_t u) {
    return __bfloat1622float2(*(__nv_bfloat162*)&u);
}

// ================= Prep kernels =================
__global__ __launch_bounds__(256) void prep_x(const float* __restrict__ X) {
    size_t i = ((size_t)blockIdx.x * 256 + threadIdx.x) * 4;
    float4 x = *(const float4*)(X + i);
    __half2 h0 = __floats2half2_rn(x.x, x.y);
    __half2 h1 = __floats2half2_rn(x.z, x.w);
    float r0 = x.x - __low2float(h0), r1 = x.y - __high2float(h0);
    float r2 = x.z - __low2float(h1), r3 = x.w - __high2float(h1);
    __half2 l0 = __floats2half2_rn(r0, r1);
    __half2 l1 = __floats2half2_rn(r2, r3);
    __half2* hi = (__half2*)(g_xhf + i);
    __half2* lo = (__half2*)(g_xhf + (size_t)T_TOK * D_IN + i);
    hi[0] = h0; hi[1] = h1;
    lo[0] = l0; lo[1] = l1;
}

__global__ __launch_bounds__(256) void prep_w(const float* __restrict__ W) {
    __shared__ float t[32][33];
    const int n0 = blockIdx.x * 32;
    const int k0 = blockIdx.y * 32;
    const int tx = threadIdx.x & 31, ty = threadIdx.x >> 5;
#pragma unroll
    for (int r = 0; r < 32; r += 8)
        t[ty + r][tx] = W[(size_t)(k0 + ty + r) * N_QKV + n0 + tx];
    __syncthreads();
#pragma unroll
    for (int r = 0; r < 32; r += 8) {
        const int nl = ty + r;
        g_wthf[(size_t)(n0 + nl) * D_IN + k0 + tx] = __float2half_rn(t[tx][nl]);
    }
}

// ================= Kernel 1: QKV GEMM (mma.sync 2xFP16) =================
// K-chunk 64. Stage = Ahi(16K) + Alo(16K) + Bhi(16K) = 48KB, 2 stages, 2 CTAs/SM.
#define PANEL_B 16384
#define STAGE_B (3 * PANEL_B)
#define GEMM_SMEM (2 * STAGE_B)

__global__ __launch_bounds__(256, 2) void qkv_gemm_mma(const float* __restrict__ bias) {
    extern __shared__ char smem[];
    const uint32_t sb = smem_to_u32(smem);
    const int tid = threadIdx.x;
    const int lane = tid & 31, wid = tid >> 5;
    const int bm = blockIdx.y * 128;
    const int bn = blockIdx.x * 128;
    const int mw = (wid >> 2) * 64;
    const int nw = (wid & 3) * 32;

    // issues cp16s only; caller commits. 3072 16B chunks, 12 per thread.
    auto load_stage = [&](int c) {
        const uint32_t st = sb + (uint32_t)(c & 1) * STAGE_B;
        const int koff = c * 64;
#pragma unroll
        for (int i = 0; i < 12; i++) {
            const int u = tid + i * 256;
            const int panel = u >> 10;            // 0: Ahi, 1: Alo, 2: Bhi
            const int row = (u >> 3) & 127;
            const int unit = u & 7;
            const uint32_t dst = st + (uint32_t)panel * PANEL_B + row * 128 +
                                 (uint32_t)((unit ^ (row & 7)) << 4);
            const __half* src = (panel < 2)
                ? (g_xhf + (size_t)panel * T_TOK * D_IN + (size_t)(bm + row) * D_IN + koff + unit * 8)
                : (g_wthf + (size_t)(bn + row) * D_IN + koff + unit * 8);
            cp16(dst, src);
        }
    };

    float acc[4][4][4];
#pragma unroll
    for (int i = 0; i < 4; i++)
#pragma unroll
        for (int j = 0; j < 4; j++)
#pragma unroll
            for (int t = 0; t < 4; t++) acc[i][j][t] = 0.f;

    const int a_r  = mw + (lane & 15);
    const int a_rx = a_r & 7;
    const int ua_hi_base = (lane >> 4);
    const int b_r  = nw + (lane & 7) + ((lane >> 4) << 3);
    const int b_rx = b_r & 7;
    const int ub_hi_base = ((lane >> 3) & 1);

    load_stage(0); cp_commit();

    for (int c = 0; c < 32; c++) {
        asm volatile("cp.async.wait_group 0;" ::: "memory");
        __syncthreads();
        if (c + 1 < 32) { load_stage(c + 1); cp_commit(); }

        const uint32_t st  = sb + (uint32_t)(c & 1) * STAGE_B;
        const uint32_t stA = st;
        const uint32_t stL = st + PANEL_B;
        const uint32_t stB = st + 2 * PANEL_B;
#pragma unroll
        for (int ks = 0; ks < 4; ks++) {
            const int ua = ks * 2 + ua_hi_base;
            const int ub = ks * 2 + ub_hi_base;
            uint32_t Bh[2][4];
#pragma unroll
            for (int p = 0; p < 2; p++) {
                const uint32_t rowb = stB + (uint32_t)(b_r + p * 16) * 128;
                ldsm4(Bh[p], rowb + (uint32_t)((ub ^ b_rx) << 4));
            }
#pragma unroll
            for (int i = 0; i < 4; i++) {
                uint32_t Ah[4], Al[4];
                const uint32_t rofs = (uint32_t)(a_r + i * 16) * 128 + (uint32_t)((ua ^ a_rx) << 4);
                ldsm4(Ah, stA + rofs);
                ldsm4(Al, stL + rofs);
#pragma unroll
                for (int j = 0; j < 4; j++) {
                    const uint32_t* bh = &Bh[j >> 1][(j & 1) * 2];
                    mma_fp16(acc[i][j], Ah, bh);
                    mma_fp16(acc[i][j], Al, bh);
                }
            }
        }
        __syncthreads();
    }

    const int ml = bm + mw + (lane >> 2);
    const int nl0 = bn + nw + (lane & 3) * 2;
    const int region = (bn < 2048) ? 0 : (bn < 3072 ? 1 : 2);

#pragma unroll
    for (int j = 0; j < 4; j++) {
        const int n = nl0 + j * 8;
        const float b0 = __ldg(bias + n), b1 = __ldg(bias + n + 1);
#pragma unroll
        for (int i = 0; i < 4; i++) {
#pragma unroll
            for (int half = 0; half < 2; half++) {
                const int m = ml + i * 16 + half * 8;
                const float v0 = acc[i][j][half * 2 + 0] + b0;
                const float v1 = acc[i][j][half * 2 + 1] + b1;
                if (region == 0) {
                    float2 o = make_float2(fmaxf(v0, 0.f) * 0.08838834764831845f,
                                           fmaxf(v1, 0.f) * 0.08838834764831845f);
                    *(float2*)&g_q[(size_t)m * 2048 + n] = o;
                } else if (region == 1) {
                    const int cc = n - 2048;
                    float s0 = fminf(__fdividef(1.f, 1.f + __expf(-v0)), 0.95f);
                    float s1 = fminf(__fdividef(1.f, 1.f + __expf(-v1)), 0.95f);
                    *(float2*)&g_k[(size_t)m * 1024 + cc] = make_float2(s0, s1);
                    *(float2*)&g_g[(size_t)m * 1024 + cc] = make_float2(__logf(1.f - s0), __logf(1.f - s1));
                } else {
                    *(float2*)&g_v[(size_t)m * 1024 + (n - 3072)] = make_float2(v0, v1);
                }
            }
        }
    }
}

// ================= Kernel 2: chunked GLA scan (tensor-core) =================
#define BC_OFF   0
#define R_OFF    33792
#define ER_OFF   34304
#define FB_OFF   34816
#define PAN_OFF  35328
#define PANEL(i) (PAN_OFF + (i) * 8192)
#define GLA_SMEM (PAN_OFF + 20 * 8192)
#define POFF(r, c) ((r) * 128 + ((((c) >> 3) ^ ((r) & 7)) << 4) + (((c) & 7) * 2))
#define PADDR(pi, r, u) (sb + PANEL(pi) + (r) * 128 + ((((u) ^ ((r) & 7))) << 4))

__global__ __launch_bounds__(256) void gla_attn(const float* __restrict__ kvc,
                                                const int* __restrict__ sidx,
                                                float* __restrict__ out) {
    extern __shared__ char smem[];
    const uint32_t sb = smem_to_u32(smem);
    float* sBc = (float*)(smem + BC_OFF);
    float* sR  = (float*)(smem + R_OFF);
    float* sER = (float*)(smem + ER_OFF);
    float* sFB = (float*)(smem + FB_OFF);

    const int vh  = blockIdx.x;
    const int h   = blockIdx.y;
    const int b   = blockIdx.z;
    const int kvh = h >> 1;
    const int tid = threadIdx.x;
    const int lane = tid & 31, wid = tid >> 5;
    const int mw = (wid >> 1) * 16;
    const int nw = (wid & 1) * 32;
    const int kw = wid * 16;
    const int skh = kw >> 6;
    const int kwl = kw & 63;
    const int rA = lane & 15, sA_ = lane >> 4;
    const int rB = (lane & 7) | ((lane >> 4) << 3);
    const int sB_ = (lane >> 3) & 1;
    const int fr = lane >> 2, fc = (lane & 3) * 2;

    // ---- init S (bf16 hi/lo) from kv_cache ----
    {
        const int slot = sidx[b];
        const float* Sg = kvc + ((size_t)slot * Hh + h) * DHh * DHh + vh * 64;
#pragma unroll
        for (int t = 0; t < 8; t++) {
            const int u = tid + t * 256;
            const int k = u >> 4, v4 = (u & 15) << 2;
            float4 s4 = *(const float4*)(Sg + (size_t)k * DHh + v4);
            uint32_t h0 = bfpack(s4.x, s4.y), h1 = bfpack(s4.z, s4.w);
            float2 hf0 = bfunpack(h0), hf1 = bfunpack(h1);
            uint32_t l0 = bfpack(s4.x - hf0.x, s4.y - hf0.y);
            uint32_t l1 = bfpack(s4.z - hf1.x, s4.w - hf1.y);
            const int off = POFF(k & 63, v4);
            *(uint2*)(smem + PANEL(12 + (k >> 6)) + off) = make_uint2(h0, h1);
            *(uint2*)(smem + PANEL(12 + 2 + (k >> 6)) + off) = make_uint2(l0, l1);
        }
    }
    __syncthreads();

    const float* qbase = g_q + (size_t)b * Ll * 2048 + h * DHh;
    const float* kbase = g_k + (size_t)b * Ll * 1024 + kvh * DHh;
    const float* gbase = g_g + (size_t)b * Ll * 1024 + kvh * DHh;
    const float* vbase = g_v + (size_t)b * Ll * 1024 + kvh * DHh + vh * 64;
    float* obase = out + (size_t)b * Ll * 2048 + h * DHh + vh * 64;

    for (int ch = 0; ch < 32; ch++) {
        const size_t row0 = (size_t)ch * 64;

        // ---- phase A: load g tile ----
#pragma unroll
        for (int t = 0; t < 8; t++) {
            const int u = tid + t * 256;
            const int i = u >> 5, k4 = (u & 31) << 2;
            float4 gv = *(const float4*)(gbase + (row0 + i) * 1024 + k4);
            *(float4*)&sBc[i * 132 + k4] = gv;
        }
        __syncthreads();

        // ---- phase B: cumsum ----
        if (tid < 128) {
            const int k = tid;
            float run = 0.f;
#pragma unroll
            for (int r = 0; r < 32; r++) {
                run += sBc[r * 132 + k];
                sBc[r * 132 + k] = run;
            }
            sR[k] = run;
            sER[k] = __expf(run);
        } else {
            const int k = tid - 128;
            float run = 0.f;
#pragma unroll
            for (int r = 32; r < 64; r++) {
                run += sBc[r * 132 + k];
                sBc[r * 132 + k] = run;
            }
            sFB[k] = __expf(run);
        }
        __syncthreads();

        // ---- phase C: exponential scalings -> bf16 hi/lo panels ----
#pragma unroll
        for (int t = 0; t < 8; t++) {
            const int u = tid + t * 256;
            const int i = u >> 5, k4 = (u & 31) << 2;
            float4 q4 = *(const float4*)(qbase + (row0 + i) * 2048 + k4);
            float4 kq = *(const float4*)(kbase + (row0 + i) * 1024 + k4);
            float qe[4], qe2[4], kd[4];
#pragma unroll
            for (int j = 0; j < 4; j++) {
                const int k = k4 + j;
                float st = sBc[i * 132 + k];
                float d = (i < 32) ? (st - sR[k]) : st;
                float e1 = __expf(fminf(d, 85.f));
                float e2 = __expf(fminf(-d, 85.f));
                float qv = (j == 0 ? q4.x : j == 1 ? q4.y : j == 2 ? q4.z : q4.w);
                float kv = (j == 0 ? kq.x : j == 1 ? kq.y : j == 2 ? kq.z : kq.w);
                qe2[j] = qv * e1;
                qe[j]  = qe2[j] * sER[k];
                kd[j]  = kv * e2;
            }
            const int kh = k4 >> 6, c = k4 & 63;
            const int off = POFF(i, c);
            {
                uint32_t h0 = bfpack(qe[0], qe[1]), h1 = bfpack(qe[2], qe[3]);
                float2 f0 = bfunpack(h0), f1 = bfunpack(h1);
                uint32_t l0 = bfpack(qe[0] - f0.x, qe[1] - f0.y);
                uint32_t l1 = bfpack(qe[2] - f1.x, qe[3] - f1.y);
                *(uint2*)(smem + PANEL(0 + kh) + off) = make_uint2(h0, h1);
                *(uint2*)(smem + PANEL(2 + kh) + off) = make_uint2(l0, l1);
            }
            {
                uint32_t h0 = bfpack(qe2[0], qe2[1]), h1 = bfpack(qe2[2], qe2[3]);
                float2 f0 = bfunpack(h0), f1 = bfunpack(h1);
                uint32_t l0 = bfpack(qe2[0] - f0.x, qe2[1] - f0.y);
                uint32_t l1 = bfpack(qe2[2] - f1.x, qe2[3] - f1.y);
                *(uint2*)(smem + PANEL(4 + kh) + off) = make_uint2(h0, h1);
                *(uint2*)(smem + PANEL(6 + kh) + off) = make_uint2(l0, l1);
            }
            {
                uint32_t h0 = bfpack(kd[0], kd[1]), h1 = bfpack(kd[2], kd[3]);
                float2 f0 = bfunpack(h0), f1 = bfunpack(h1);
                uint32_t l0 = bfpack(kd[0] - f0.x, kd[1] - f0.y);
                uint32_t l1 = bfpack(kd[2] - f1.x, kd[3] - f1.y);
                *(uint2*)(smem + PANEL(8 + kh) + off) = make_uint2(h0, h1);
                *(uint2*)(smem + PANEL(10 + kh) + off) = make_uint2(l0, l1);
            }
        }
#pragma unroll
        for (int t = 0; t < 4; t++) {
            const int u = tid + t * 256;
            const int i = u >> 4, v4 = (u & 15) << 2;
            float4 vv = *(const float4*)(vbase + (row0 + i) * 1024 + v4);
            uint32_t h0 = bfpack(vv.x, vv.y), h1 = bfpack(vv.z, vv.w);
            float2 f0 = bfunpack(h0), f1 = bfunpack(h1);
            uint32_t l0 = bfpack(vv.x - f0.x, vv.y - f0.y);
            uint32_t l1 = bfpack(vv.z - f1.x, vv.w - f1.y);
            const int off = POFF(i, v4);
            *(uint2*)(smem + PANEL(16) + off) = make_uint2(h0, h1);
            *(uint2*)(smem + PANEL(17) + off) = make_uint2(l0, l1);
        }
        __syncthreads();

        // ---- phase D: GEMM2 (A = Qe2 @ Kd^T) + GEMM1 (o = Qe @ S) ----
        float accO[4][4];
        {
            float acc2[4][4];
#pragma unroll
            for (int t = 0; t < 4; t++)
#pragma unroll
                for (int e = 0; e < 4; e++) acc2[t][e] = 0.f;
#pragma unroll
            for (int kk = 0; kk < 8; kk++) {
                const int kh = kk >> 2, u0 = (kk & 3) * 2;
                uint32_t Ah[4], Al[4];
                ldsm4(Ah, PADDR(4 + kh, mw + rA, u0 + sA_));
                ldsm4(Al, PADDR(6 + kh, mw + rA, u0 + sA_));
#pragma unroll
                for (int g = 0; g < 2; g++) {
                    uint32_t Bh[4], Bl[4];
                    const int rowb = nw + g * 16 + rB;
                    ldsm4(Bh, PADDR(8 + kh, rowb, u0 + sB_));
                    ldsm4(Bl, PADDR(10 + kh, rowb, u0 + sB_));
#pragma unroll
                    for (int n8 = 0; n8 < 2; n8++) {
                        float* d = acc2[g * 2 + n8];
                        mma_bf16(d, Ah, Bh + n8 * 2);
                        mma_bf16(d, Ah, Bl + n8 * 2);
                        mma_bf16(d, Al, Bh + n8 * 2);
                    }
                }
            }
#pragma unroll
            for (int t = 0; t < 4; t++) {
                const int j = nw + t * 8 + fc;
#pragma unroll
                for (int half = 0; half < 2; half++) {
                    const int i = mw + fr + half * 8;
                    float x = (j <= i) ? acc2[t][half * 2 + 0] : 0.f;
                    float y = (j + 1 <= i) ? acc2[t][half * 2 + 1] : 0.f;
                    uint32_t hb = bfpack(x, y);
                    float2 hf = bfunpack(hb);
                    uint32_t lb = bfpack(x - hf.x, y - hf.y);
                    const int off = POFF(i, j);
                    *(uint32_t*)(smem + PANEL(18) + off) = hb;
                    *(uint32_t*)(smem + PANEL(19) + off) = lb;
                }
            }
#pragma unroll
            for (int t = 0; t < 4; t++)
#pragma unroll
                for (int e = 0; e < 4; e++) accO[t][e] = 0.f;
#pragma unroll
            for (int kk = 0; kk < 8; kk++) {
                const int kh = kk >> 2, u0 = (kk & 3) * 2;
                uint32_t Ah[4], Al[4];
                ldsm4(Ah, PADDR(0 + kh, mw + rA, u0 + sA_));
                ldsm4(Al, PADDR(2 + kh, mw + rA, u0 + sA_));
                const int rowS = (kk & 3) * 16 + rA;
#pragma unroll
                for (int g = 0; g < 2; g++) {
                    const int un = (nw >> 3) + g * 2 + sA_;
                    uint32_t Bh[4], Bl[4];
                    ldsm4t(Bh, PADDR(12 + kh, rowS, un));
                    ldsm4t(Bl, PADDR(14 + kh, rowS, un));
#pragma unroll
                    for (int n8 = 0; n8 < 2; n8++) {
                        float* d = accO[g * 2 + n8];
                        mma_bf16(d, Ah, Bh + n8 * 2);
                        mma_bf16(d, Ah, Bl + n8 * 2);
                        mma_bf16(d, Al, Bh + n8 * 2);
                    }
                }
            }
        }
        __syncthreads();

        // ---- phase F: GEMM3 (o += A @ V); write o; state update ----
#pragma unroll
        for (int kk = 0; kk < 4; kk++) {
            const int u0 = kk * 2;
            uint32_t Ah[4], Al[4];
            ldsm4(Ah, PADDR(18, mw + rA, u0 + sA_));
            ldsm4(Al, PADDR(19, mw + rA, u0 + sA_));
            const int rowV = kk * 16 + rA;
#pragma unroll
            for (int g = 0; g < 2; g++) {
                const int un = (nw >> 3) + g * 2 + sA_;
                uint32_t Bh[4], Bl[4];
                ldsm4t(Bh, PADDR(16, rowV, un));
                ldsm4t(Bl, PADDR(17, rowV, un));
#pragma unroll
                for (int n8 = 0; n8 < 2; n8++) {
                    float* d = accO[g * 2 + n8];
                    mma_bf16(d, Ah, Bh + n8 * 2);
                    mma_bf16(d, Ah, Bl + n8 * 2);
                    mma_bf16(d, Al, Bh + n8 * 2);
                }
            }
        }
#pragma unroll
        for (int t = 0; t < 4; t++) {
            const int v = nw + t * 8 + fc;
#pragma unroll
            for (int half = 0; half < 2; half++) {
                const int i = mw + fr + half * 8;
                *(float2*)(obase + (row0 + i) * 2048 + v) =
                    make_float2(accO[t][half * 2], accO[t][half * 2 + 1]);
            }
        }
        // state update: accS = eR*S; accS += Kd^T @ V; accS *= fb
        {
            float accS[8][4];
#pragma unroll
            for (int half = 0; half < 2; half++) {
                const int krow = kw + fr + half * 8;
                const float er = sER[krow];
#pragma unroll
                for (int t = 0; t < 8; t++) {
                    const int v = t * 8 + fc;
                    const int off = POFF(krow & 63, v);
                    float2 hf = bfunpack(*(uint32_t*)(smem + PANEL(12 + skh) + off));
                    float2 lf = bfunpack(*(uint32_t*)(smem + PANEL(14 + skh) + off));
                    accS[t][half * 2 + 0] = (hf.x + lf.x) * er;
                    accS[t][half * 2 + 1] = (hf.y + lf.y) * er;
                }
            }
#pragma unroll
            for (int kk = 0; kk < 4; kk++) {
                const int rowJ = rB + kk * 16;
                const int unM = (kwl >> 3) + sB_;
                uint32_t Ah[4], Al[4];
                ldsm4t(Ah, PADDR(8 + skh, rowJ, unM));
                ldsm4t(Al, PADDR(10 + skh, rowJ, unM));
                const int rowV = kk * 16 + rA;
#pragma unroll
                for (int g = 0; g < 4; g++) {
                    const int un = g * 2 + sA_;
                    uint32_t Bh[4], Bl[4];
                    ldsm4t(Bh, PADDR(16, rowV, un));
                    ldsm4t(Bl, PADDR(17, rowV, un));
#pragma unroll
                    for (int n8 = 0; n8 < 2; n8++) {
                        float* d = accS[g * 2 + n8];
                        mma_bf16(d, Ah, Bh + n8 * 2);
                        mma_bf16(d, Ah, Bl + n8 * 2);
                        mma_bf16(d, Al, Bh + n8 * 2);
                    }
                }
            }
#pragma unroll
            for (int half = 0; half < 2; half++) {
                const int krow = kw + fr + half * 8;
                const float fb = sFB[krow];
#pragma unroll
                for (int t = 0; t < 8; t++) {
                    const int v = t * 8 + fc;
                    float x = accS[t][half * 2 + 0] * fb, y = accS[t][half * 2 + 1] * fb;
                    uint32_t hb = bfpack(x, y);
                    float2 hf = bfunpack(hb);
                    uint32_t lb = bfpack(x - hf.x, y - hf.y);
                    const int off = POFF(krow & 63, v);
                    *(uint32_t*)(smem + PANEL(12 + skh) + off) = hb;
                    *(uint32_t*)(smem + PANEL(14 + skh) + off) = lb;
                }
            }
        }
        __syncthreads();
    }
}

// ---------------- launch ----------------
extern "C" void kernel_launch(void* const* d_in, const int* in_sizes, int n_in,
                              void* d_out, int out_size) {
    const float* X    = (const float*)d_in[0];
    const float* W    = (const float*)d_in[1];
    const float* bias = (const float*)d_in[2];
    const float* kvc  = (const float*)d_in[3];
    const int*   sidx = (const int*)d_in[4];
    float* out = (float*)d_out;

    prep_x<<<(T_TOK * D_IN) / (256 * 4), 256>>>(X);
    prep_w<<<dim3(N_QKV / 32, D_IN / 32), 256>>>(W);

    cudaFuncSetAttribute(qkv_gemm_mma, cudaFuncAttributeMaxDynamicSharedMemorySize, GEMM_SMEM);
    dim3 gg(N_QKV / 128, T_TOK / 128);
    qkv_gemm_mma<<<gg, 256, GEMM_SMEM>>>(bias);

    cudaFuncSetAttribute(gla_attn, cudaFuncAttributeMaxDynamicSharedMemorySize, GLA_SMEM);
    dim3 ga(2, Hh, Bb);
    gla_attn<<<ga, 256, GLA_SMEM>>>(kvc, sidx, out);
}

// round 11
// speedup vs baseline: 2.2580x; 1.3995x over previous
#include <cuda_runtime.h>
#include <cuda_bf16.h>
#include <cuda_fp16.h>
#include <math.h>
#include <stdint.h>

// Problem constants
#define T_TOK 8192
#define D_IN  2048
#define N_QKV 4096
#define Hh    16
#define KVHh  8
#define DHh   128
#define Bb    4
#define Ll    2048
#define Cc    64

// Scratch (device globals: allocation-free per harness rules)
__device__ float g_q[(size_t)T_TOK * 2048];
__device__ float g_k[(size_t)T_TOK * 1024];
__device__ float g_g[(size_t)T_TOK * 1024];
__device__ float g_v[(size_t)T_TOK * 1024];
// fp16 operands for the QKV GEMM (single precision plane each)
__device__ __align__(1024) __half g_xhf[(size_t)T_TOK * D_IN];   // [8192][2048]
__device__ __align__(1024) __half g_wthf[(size_t)N_QKV * D_IN];  // [4096][2048] (W^T)

// ================= helpers =================
__device__ __forceinline__ uint32_t smem_to_u32(const void* p) {
    uint32_t a;
    asm("{ .reg .u64 t; cvta.to.shared.u64 t, %1; cvt.u32.u64 %0, t; }" : "=r"(a) : "l"(p));
    return a;
}
__device__ __forceinline__ void cp16(uint32_t dst, const void* src) {
    asm volatile("cp.async.cg.shared.global [%0], [%1], 16;\n" :: "r"(dst), "l"(src));
}
__device__ __forceinline__ void cp_commit() { asm volatile("cp.async.commit_group;\n" ::: "memory"); }
__device__ __forceinline__ void ldsm4(uint32_t* r, uint32_t addr) {
    asm volatile("ldmatrix.sync.aligned.m8n8.x4.shared.b16 {%0,%1,%2,%3}, [%4];"
        : "=r"(r[0]), "=r"(r[1]), "=r"(r[2]), "=r"(r[3]) : "r"(addr));
}
__device__ __forceinline__ void ldsm4t(uint32_t* r, uint32_t addr) {
    asm volatile("ldmatrix.sync.aligned.m8n8.x4.trans.shared.b16 {%0,%1,%2,%3}, [%4];"
        : "=r"(r[0]), "=r"(r[1]), "=r"(r[2]), "=r"(r[3]) : "r"(addr));
}
__device__ __forceinline__ void mma_bf16(float* d, const uint32_t* a, const uint32_t* b) {
    asm volatile("mma.sync.aligned.m16n8k16.row.col.f32.bf16.bf16.f32 "
        "{%0,%1,%2,%3}, {%4,%5,%6,%7}, {%8,%9}, {%0,%1,%2,%3};"
        : "+f"(d[0]), "+f"(d[1]), "+f"(d[2]), "+f"(d[3])
        : "r"(a[0]), "r"(a[1]), "r"(a[2]), "r"(a[3]), "r"(b[0]), "r"(b[1]));
}
__device__ __forceinline__ void mma_fp16(float* d, const uint32_t* a, const uint32_t* b) {
    asm volatile("mma.sync.aligned.m16n8k16.row.col.f32.f16.f16.f32 "
        "{%0,%1,%2,%3}, {%4,%5,%6,%7}, {%8,%9}, {%0,%1,%2,%3};"
        : "+f"(d[0]), "+f"(d[1]), "+f"(d[2]), "+f"(d[3])
        : "r"(a[0]), "r"(a[1]), "r"(a[2]), "r"(a[3]), "r"(b[0]), "r"(b[1]));
}
__device__ __forceinline__ uint32_t bfpack(float x, float y) {
    __nv_bfloat162 h = __floats2bfloat162_rn(x, y);
    return *(uint32_t*)&h;
}
__device__ __forceinline__ float2 bfunpack(uint32_t u) {
    return __bfloat1622float2(*(__nv_bfloat162*)&u);
}

// ================= Prep kernels =================
__global__ __launch_bounds__(256) void prep_x(const float* __restrict__ X) {
    size_t i = ((size_t)blockIdx.x * 256 + threadIdx.x) * 4;
    float4 x = *(const float4*)(X + i);
    __half2* dst = (__half2*)(g_xhf + i);
    dst[0] = __floats2half2_rn(x.x, x.y);
    dst[1] = __floats2half2_rn(x.z, x.w);
}

__global__ __launch_bounds__(256) void prep_w(const float* __restrict__ W) {
    __shared__ float t[32][33];
    const int n0 = blockIdx.x * 32;
    const int k0 = blockIdx.y * 32;
    const int tx = threadIdx.x & 31, ty = threadIdx.x >> 5;
#pragma unroll
    for (int r = 0; r < 32; r += 8)
        t[ty + r][tx] = W[(size_t)(k0 + ty + r) * N_QKV + n0 + tx];
    __syncthreads();
#pragma unroll
    for (int r = 0; r < 32; r += 8) {
        const int nl = ty + r;
        g_wthf[(size_t)(n0 + nl) * D_IN + k0 + tx] = __float2half_rn(t[tx][nl]);
    }
}

// ================= Kernel 1: QKV GEMM (mma.sync 1xFP16) =================
// K-chunk 64. Stage = A(16K) + B(16K) = 32KB, 3 stages, 2 CTAs/SM,
// one __syncthreads per chunk, wait_group 1 (prefetch depth 2).
#define PANEL_B 16384
#define STAGE_B (2 * PANEL_B)
#define GEMM_SMEM (3 * STAGE_B)

__global__ __launch_bounds__(256, 2) void qkv_gemm_mma(const float* __restrict__ bias) {
    extern __shared__ char smem[];
    const uint32_t sb = smem_to_u32(smem);
    const int tid = threadIdx.x;
    const int lane = tid & 31, wid = tid >> 5;
    const int bm = blockIdx.y * 128;
    const int bn = blockIdx.x * 128;
    const int mw = (wid >> 2) * 64;
    const int nw = (wid & 3) * 32;

    // issues cp16s only; caller commits. 2048 16B chunks, 8 per thread.
    auto load_stage = [&](int c) {
        const uint32_t st = sb + (uint32_t)(c % 3) * STAGE_B;
        const int koff = c * 64;
#pragma unroll
        for (int i = 0; i < 8; i++) {
            const int u = tid + i * 256;
            const int panel = u >> 10;            // 0: A, 1: B
            const int row = (u >> 3) & 127;
            const int unit = u & 7;
            const uint32_t dst = st + (uint32_t)panel * PANEL_B + row * 128 +
                                 (uint32_t)((unit ^ (row & 7)) << 4);
            const __half* src = (panel == 0)
                ? (g_xhf + (size_t)(bm + row) * D_IN + koff + unit * 8)
                : (g_wthf + (size_t)(bn + row) * D_IN + koff + unit * 8);
            cp16(dst, src);
        }
    };

    float acc[4][4][4];
#pragma unroll
    for (int i = 0; i < 4; i++)
#pragma unroll
        for (int j = 0; j < 4; j++)
#pragma unroll
            for (int t = 0; t < 4; t++) acc[i][j][t] = 0.f;

    const int a_r  = mw + (lane & 15);
    const int a_rx = a_r & 7;
    const int ua_hi_base = (lane >> 4);
    const int b_r  = nw + (lane & 7) + ((lane >> 4) << 3);
    const int b_rx = b_r & 7;
    const int ub_hi_base = ((lane >> 3) & 1);

    load_stage(0); cp_commit();
    load_stage(1); cp_commit();

    for (int c = 0; c < 32; c++) {
        // wait for group c (group c+1 may stay in flight), then make all
        // threads' copies visible to all warps.
        asm volatile("cp.async.wait_group 1;" ::: "memory");
        __syncthreads();
        // stage (c+2)%3 was last read in chunk c-1; every warp passed the
        // sync above only after finishing that compute, so overwrite is safe.
        if (c + 2 < 32) { load_stage(c + 2); cp_commit(); }

        const uint32_t stA = sb + (uint32_t)(c % 3) * STAGE_B;
        const uint32_t stB = stA + PANEL_B;
#pragma unroll
        for (int ks = 0; ks < 4; ks++) {
            const int ua = ks * 2 + ua_hi_base;
            const int ub = ks * 2 + ub_hi_base;
            uint32_t Bh[2][4];
#pragma unroll
            for (int p = 0; p < 2; p++) {
                const uint32_t rowb = stB + (uint32_t)(b_r + p * 16) * 128;
                ldsm4(Bh[p], rowb + (uint32_t)((ub ^ b_rx) << 4));
            }
#pragma unroll
            for (int i = 0; i < 4; i++) {
                uint32_t Ah[4];
                const uint32_t rofs = (uint32_t)(a_r + i * 16) * 128 + (uint32_t)((ua ^ a_rx) << 4);
                ldsm4(Ah, stA + rofs);
#pragma unroll
                for (int j = 0; j < 4; j++) {
                    mma_fp16(acc[i][j], Ah, &Bh[j >> 1][(j & 1) * 2]);
                }
            }
        }
        // no bottom sync: next iteration's top sync orders readers before
        // the eventual overwrite of this stage.
    }

    const int ml = bm + mw + (lane >> 2);
    const int nl0 = bn + nw + (lane & 3) * 2;
    const int region = (bn < 2048) ? 0 : (bn < 3072 ? 1 : 2);

#pragma unroll
    for (int j = 0; j < 4; j++) {
        const int n = nl0 + j * 8;
        const float b0 = __ldg(bias + n), b1 = __ldg(bias + n + 1);
#pragma unroll
        for (int i = 0; i < 4; i++) {
#pragma unroll
            for (int half = 0; half < 2; half++) {
                const int m = ml + i * 16 + half * 8;
                const float v0 = acc[i][j][half * 2 + 0] + b0;
                const float v1 = acc[i][j][half * 2 + 1] + b1;
                if (region == 0) {
                    float2 o = make_float2(fmaxf(v0, 0.f) * 0.08838834764831845f,
                                           fmaxf(v1, 0.f) * 0.08838834764831845f);
                    *(float2*)&g_q[(size_t)m * 2048 + n] = o;
                } else if (region == 1) {
                    const int cc = n - 2048;
                    float s0 = fminf(__fdividef(1.f, 1.f + __expf(-v0)), 0.95f);
                    float s1 = fminf(__fdividef(1.f, 1.f + __expf(-v1)), 0.95f);
                    *(float2*)&g_k[(size_t)m * 1024 + cc] = make_float2(s0, s1);
                    *(float2*)&g_g[(size_t)m * 1024 + cc] = make_float2(__logf(1.f - s0), __logf(1.f - s1));
                } else {
                    *(float2*)&g_v[(size_t)m * 1024 + (n - 3072)] = make_float2(v0, v1);
                }
            }
        }
    }
}

// ================= Kernel 2: chunked GLA scan (tensor-core) =================
#define BC_OFF   0
#define R_OFF    33792
#define ER_OFF   34304
#define FB_OFF   34816
#define PAN_OFF  35328
#define PANEL(i) (PAN_OFF + (i) * 8192)
#define GLA_SMEM (PAN_OFF + 20 * 8192)
#define POFF(r, c) ((r) * 128 + ((((c) >> 3) ^ ((r) & 7)) << 4) + (((c) & 7) * 2))
#define PADDR(pi, r, u) (sb + PANEL(pi) + (r) * 128 + ((((u) ^ ((r) & 7))) << 4))

__global__ __launch_bounds__(256) void gla_attn(const float* __restrict__ kvc,
                                                const int* __restrict__ sidx,
                                                float* __restrict__ out) {
    extern __shared__ char smem[];
    const uint32_t sb = smem_to_u32(smem);
    float* sBc = (float*)(smem + BC_OFF);
    float* sR  = (float*)(smem + R_OFF);
    float* sER = (float*)(smem + ER_OFF);
    float* sFB = (float*)(smem + FB_OFF);

    const int vh  = blockIdx.x;
    const int h   = blockIdx.y;
    const int b   = blockIdx.z;
    const int kvh = h >> 1;
    const int tid = threadIdx.x;
    const int lane = tid & 31, wid = tid >> 5;
    const int mw = (wid >> 1) * 16;
    const int nw = (wid & 1) * 32;
    const int kw = wid * 16;
    const int skh = kw >> 6;
    const int kwl = kw & 63;
    const int rA = lane & 15, sA_ = lane >> 4;
    const int rB = (lane & 7) | ((lane >> 4) << 3);
    const int sB_ = (lane >> 3) & 1;
    const int fr = lane >> 2, fc = (lane & 3) * 2;

    // ---- init S (bf16 hi/lo) from kv_cache ----
    {
        const int slot = sidx[b];
        const float* Sg = kvc + ((size_t)slot * Hh + h) * DHh * DHh + vh * 64;
#pragma unroll
        for (int t = 0; t < 8; t++) {
            const int u = tid + t * 256;
            const int k = u >> 4, v4 = (u & 15) << 2;
            float4 s4 = *(const float4*)(Sg + (size_t)k * DHh + v4);
            uint32_t h0 = bfpack(s4.x, s4.y), h1 = bfpack(s4.z, s4.w);
            float2 hf0 = bfunpack(h0), hf1 = bfunpack(h1);
            uint32_t l0 = bfpack(s4.x - hf0.x, s4.y - hf0.y);
            uint32_t l1 = bfpack(s4.z - hf1.x, s4.w - hf1.y);
            const int off = POFF(k & 63, v4);
            *(uint2*)(smem + PANEL(12 + (k >> 6)) + off) = make_uint2(h0, h1);
            *(uint2*)(smem + PANEL(12 + 2 + (k >> 6)) + off) = make_uint2(l0, l1);
        }
    }
    __syncthreads();

    const float* qbase = g_q + (size_t)b * Ll * 2048 + h * DHh;
    const float* kbase = g_k + (size_t)b * Ll * 1024 + kvh * DHh;
    const float* gbase = g_g + (size_t)b * Ll * 1024 + kvh * DHh;
    const float* vbase = g_v + (size_t)b * Ll * 1024 + kvh * DHh + vh * 64;
    float* obase = out + (size_t)b * Ll * 2048 + h * DHh + vh * 64;

    for (int ch = 0; ch < 32; ch++) {
        const size_t row0 = (size_t)ch * 64;

        // ---- phase A: load g tile ----
#pragma unroll
        for (int t = 0; t < 8; t++) {
            const int u = tid + t * 256;
            const int i = u >> 5, k4 = (u & 31) << 2;
            float4 gv = *(const float4*)(gbase + (row0 + i) * 1024 + k4);
            *(float4*)&sBc[i * 132 + k4] = gv;
        }
        __syncthreads();

        // ---- phase B: cumsum ----
        if (tid < 128) {
            const int k = tid;
            float run = 0.f;
#pragma unroll
            for (int r = 0; r < 32; r++) {
                run += sBc[r * 132 + k];
                sBc[r * 132 + k] = run;
            }
            sR[k] = run;
            sER[k] = __expf(run);
        } else {
            const int k = tid - 128;
            float run = 0.f;
#pragma unroll
            for (int r = 32; r < 64; r++) {
                run += sBc[r * 132 + k];
                sBc[r * 132 + k] = run;
            }
            sFB[k] = __expf(run);
        }
        __syncthreads();

        // ---- phase C: exponential scalings -> bf16 hi/lo panels ----
#pragma unroll
        for (int t = 0; t < 8; t++) {
            const int u = tid + t * 256;
            const int i = u >> 5, k4 = (u & 31) << 2;
            float4 q4 = *(const float4*)(qbase + (row0 + i) * 2048 + k4);
            float4 kq = *(const float4*)(kbase + (row0 + i) * 1024 + k4);
            float qe[4], qe2[4], kd[4];
#pragma unroll
            for (int j = 0; j < 4; j++) {
                const int k = k4 + j;
                float st = sBc[i * 132 + k];
                float d = (i < 32) ? (st - sR[k]) : st;
                float e1 = __expf(fminf(d, 85.f));
                float e2 = __expf(fminf(-d, 85.f));
                float qv = (j == 0 ? q4.x : j == 1 ? q4.y : j == 2 ? q4.z : q4.w);
                float kv = (j == 0 ? kq.x : j == 1 ? kq.y : j == 2 ? kq.z : kq.w);
                qe2[j] = qv * e1;
                qe[j]  = qe2[j] * sER[k];
                kd[j]  = kv * e2;
            }
            const int kh = k4 >> 6, c = k4 & 63;
            const int off = POFF(i, c);
            {
                uint32_t h0 = bfpack(qe[0], qe[1]), h1 = bfpack(qe[2], qe[3]);
                float2 f0 = bfunpack(h0), f1 = bfunpack(h1);
                uint32_t l0 = bfpack(qe[0] - f0.x, qe[1] - f0.y);
                uint32_t l1 = bfpack(qe[2] - f1.x, qe[3] - f1.y);
                *(uint2*)(smem + PANEL(0 + kh) + off) = make_uint2(h0, h1);
                *(uint2*)(smem + PANEL(2 + kh) + off) = make_uint2(l0, l1);
            }
            {
                uint32_t h0 = bfpack(qe2[0], qe2[1]), h1 = bfpack(qe2[2], qe2[3]);
                float2 f0 = bfunpack(h0), f1 = bfunpack(h1);
                uint32_t l0 = bfpack(qe2[0] - f0.x, qe2[1] - f0.y);
                uint32_t l1 = bfpack(qe2[2] - f1.x, qe2[3] - f1.y);
                *(uint2*)(smem + PANEL(4 + kh) + off) = make_uint2(h0, h1);
                *(uint2*)(smem + PANEL(6 + kh) + off) = make_uint2(l0, l1);
            }
            {
                uint32_t h0 = bfpack(kd[0], kd[1]), h1 = bfpack(kd[2], kd[3]);
                float2 f0 = bfunpack(h0), f1 = bfunpack(h1);
                uint32_t l0 = bfpack(kd[0] - f0.x, kd[1] - f0.y);
                uint32_t l1 = bfpack(kd[2] - f1.x, kd[3] - f1.y);
                *(uint2*)(smem + PANEL(8 + kh) + off) = make_uint2(h0, h1);
                *(uint2*)(smem + PANEL(10 + kh) + off) = make_uint2(l0, l1);
            }
        }
#pragma unroll
        for (int t = 0; t < 4; t++) {
            const int u = tid + t * 256;
            const int i = u >> 4, v4 = (u & 15) << 2;
            float4 vv = *(const float4*)(vbase + (row0 + i) * 1024 + v4);
            uint32_t h0 = bfpack(vv.x, vv.y), h1 = bfpack(vv.z, vv.w);
            float2 f0 = bfunpack(h0), f1 = bfunpack(h1);
            uint32_t l0 = bfpack(vv.x - f0.x, vv.y - f0.y);
            uint32_t l1 = bfpack(vv.z - f1.x, vv.w - f1.y);
            const int off = POFF(i, v4);
            *(uint2*)(smem + PANEL(16) + off) = make_uint2(h0, h1);
            *(uint2*)(smem + PANEL(17) + off) = make_uint2(l0, l1);
        }
        __syncthreads();

        // ---- phase D: GEMM2 (A = Qe2 @ Kd^T) + GEMM1 (o = Qe @ S) ----
        float accO[4][4];
        {
            float acc2[4][4];
#pragma unroll
            for (int t = 0; t < 4; t++)
#pragma unroll
                for (int e = 0; e < 4; e++) acc2[t][e] = 0.f;
#pragma unroll
            for (int kk = 0; kk < 8; kk++) {
                const int kh = kk >> 2, u0 = (kk & 3) * 2;
                uint32_t Ah[4], Al[4];
                ldsm4(Ah, PADDR(4 + kh, mw + rA, u0 + sA_));
                ldsm4(Al, PADDR(6 + kh, mw + rA, u0 + sA_));
#pragma unroll
                for (int g = 0; g < 2; g++) {
                    uint32_t Bh[4], Bl[4];
                    const int rowb = nw + g * 16 + rB;
                    ldsm4(Bh, PADDR(8 + kh, rowb, u0 + sB_));
                    ldsm4(Bl, PADDR(10 + kh, rowb, u0 + sB_));
#pragma unroll
                    for (int n8 = 0; n8 < 2; n8++) {
                        float* d = acc2[g * 2 + n8];
                        mma_bf16(d, Ah, Bh + n8 * 2);
                        mma_bf16(d, Ah, Bl + n8 * 2);
                        mma_bf16(d, Al, Bh + n8 * 2);
                    }
                }
            }
#pragma unroll
            for (int t = 0; t < 4; t++) {
                const int j = nw + t * 8 + fc;
#pragma unroll
                for (int half = 0; half < 2; half++) {
                    const int i = mw + fr + half * 8;
                    float x = (j <= i) ? acc2[t][half * 2 + 0] : 0.f;
                    float y = (j + 1 <= i) ? acc2[t][half * 2 + 1] : 0.f;
                    uint32_t hb = bfpack(x, y);
                    float2 hf = bfunpack(hb);
                    uint32_t lb = bfpack(x - hf.x, y - hf.y);
                    const int off = POFF(i, j);
                    *(uint32_t*)(smem + PANEL(18) + off) = hb;
                    *(uint32_t*)(smem + PANEL(19) + off) = lb;
                }
            }
#pragma unroll
            for (int t = 0; t < 4; t++)
#pragma unroll
                for (int e = 0; e < 4; e++) accO[t][e] = 0.f;
#pragma unroll
            for (int kk = 0; kk < 8; kk++) {
                const int kh = kk >> 2, u0 = (kk & 3) * 2;
                uint32_t Ah[4], Al[4];
                ldsm4(Ah, PADDR(0 + kh, mw + rA, u0 + sA_));
                ldsm4(Al, PADDR(2 + kh, mw + rA, u0 + sA_));
                const int rowS = (kk & 3) * 16 + rA;
#pragma unroll
                for (int g = 0; g < 2; g++) {
                    const int un = (nw >> 3) + g * 2 + sA_;
                    uint32_t Bh[4], Bl[4];
                    ldsm4t(Bh, PADDR(12 + kh, rowS, un));
                    ldsm4t(Bl, PADDR(14 + kh, rowS, un));
#pragma unroll
                    for (int n8 = 0; n8 < 2; n8++) {
                        float* d = accO[g * 2 + n8];
                        mma_bf16(d, Ah, Bh + n8 * 2);
                        mma_bf16(d, Ah, Bl + n8 * 2);
                        mma_bf16(d, Al, Bh + n8 * 2);
                    }
                }
            }
        }
        __syncthreads();

        // ---- phase F: GEMM3 (o += A @ V); write o; state update ----
#pragma unroll
        for (int kk = 0; kk < 4; kk++) {
            const int u0 = kk * 2;
            uint32_t Ah[4], Al[4];
            ldsm4(Ah, PADDR(18, mw + rA, u0 + sA_));
            ldsm4(Al, PADDR(19, mw + rA, u0 + sA_));
            const int rowV = kk * 16 + rA;
#pragma unroll
            for (int g = 0; g < 2; g++) {
                const int un = (nw >> 3) + g * 2 + sA_;
                uint32_t Bh[4], Bl[4];
                ldsm4t(Bh, PADDR(16, rowV, un));
                ldsm4t(Bl, PADDR(17, rowV, un));
#pragma unroll
                for (int n8 = 0; n8 < 2; n8++) {
                    float* d = accO[g * 2 + n8];
                    mma_bf16(d, Ah, Bh + n8 * 2);
                    mma_bf16(d, Ah, Bl + n8 * 2);
                    mma_bf16(d, Al, Bh + n8 * 2);
                }
            }
        }
#pragma unroll
        for (int t = 0; t < 4; t++) {
            const int v = nw + t * 8 + fc;
#pragma unroll
            for (int half = 0; half < 2; half++) {
                const int i = mw + fr + half * 8;
                *(float2*)(obase + (row0 + i) * 2048 + v) =
                    make_float2(accO[t][half * 2], accO[t][half * 2 + 1]);
            }
        }
        // state update: accS = eR*S; accS += Kd^T @ V; accS *= fb
        {
            float accS[8][4];
#pragma unroll
            for (int half = 0; half < 2; half++) {
                const int krow = kw + fr + half * 8;
                const float er = sER[krow];
#pragma unroll
                for (int t = 0; t < 8; t++) {
                    const int v = t * 8 + fc;
                    const int off = POFF(krow & 63, v);
                    float2 hf = bfunpack(*(uint32_t*)(smem + PANEL(12 + skh) + off));
                    float2 lf = bfunpack(*(uint32_t*)(smem + PANEL(14 + skh) + off));
                    accS[t][half * 2 + 0] = (hf.x + lf.x) * er;
                    accS[t][half * 2 + 1] = (hf.y + lf.y) * er;
                }
            }
#pragma unroll
            for (int kk = 0; kk < 4; kk++) {
                const int rowJ = rB + kk * 16;
                const int unM = (kwl >> 3) + sB_;
                uint32_t Ah[4], Al[4];
                ldsm4t(Ah, PADDR(8 + skh, rowJ, unM));
                ldsm4t(Al, PADDR(10 + skh, rowJ, unM));
                const int rowV = kk * 16 + rA;
#pragma unroll
                for (int g = 0; g < 4; g++) {
                    const int un = g * 2 + sA_;
                    uint32_t Bh[4], Bl[4];
                    ldsm4t(Bh, PADDR(16, rowV, un));
                    ldsm4t(Bl, PADDR(17, rowV, un));
#pragma unroll
                    for (int n8 = 0; n8 < 2; n8++) {
                        float* d = accS[g * 2 + n8];
                        mma_bf16(d, Ah, Bh + n8 * 2);
                        mma_bf16(d, Ah, Bl + n8 * 2);
                        mma_bf16(d, Al, Bh + n8 * 2);
                    }
                }
            }
#pragma unroll
            for (int half = 0; half < 2; half++) {
                const int krow = kw + fr + half * 8;
                const float fb = sFB[krow];
#pragma unroll
                for (int t = 0; t < 8; t++) {
                    const int v = t * 8 + fc;
                    float x = accS[t][half * 2 + 0] * fb, y = accS[t][half * 2 + 1] * fb;
                    uint32_t hb = bfpack(x, y);
                    float2 hf = bfunpack(hb);
                    uint32_t lb = bfpack(x - hf.x, y - hf.y);
                    const int off = POFF(krow & 63, v);
                    *(uint32_t*)(smem + PANEL(12 + skh) + off) = hb;
                    *(uint32_t*)(smem + PANEL(14 + skh) + off) = lb;
                }
            }
        }
        __syncthreads();
    }
}

// ---------------- launch ----------------
extern "C" void kernel_launch(void* const* d_in, const int* in_sizes, int n_in,
                              void* d_out, int out_size) {
    const float* X    = (const float*)d_in[0];
    const float* W    = (const float*)d_in[1];
    const float* bias = (const float*)d_in[2];
    const float* kvc  = (const float*)d_in[3];
    const int*   sidx = (const int*)d_in[4];
    float* out = (float*)d_out;

    prep_x<<<(T_TOK * D_IN) / (256 * 4), 256>>>(X);
    prep_w<<<dim3(N_QKV / 32, D_IN / 32), 256>>>(W);

    cudaFuncSetAttribute(qkv_gemm_mma, cudaFuncAttributeMaxDynamicSharedMemorySize, GEMM_SMEM);
    dim3 gg(N_QKV / 128, T_TOK / 128);
    qkv_gemm_mma<<<gg, 256, GEMM_SMEM>>>(bias);

    cudaFuncSetAttribute(gla_attn, cudaFuncAttributeMaxDynamicSharedMemorySize, GLA_SMEM);
    dim3 ga(2, Hh, Bb);
    gla_attn<<<ga, 256, GLA_SMEM>>>(kvc, sidx, out);
}